// round 1
// baseline (speedup 1.0000x reference)
#include <cuda_runtime.h>
#include <cuda_bf16.h>
#include <math_constants.h>

// Problem constants
#define BB 4
#define SS 2048
#define DD 1024
#define HH 16
#define DK 64
#define MM (BB*SS)          // 8192 rows

// Scratch in device globals (no allocation allowed)
__device__ float g_Q[BB*HH*SS*DK];
__device__ float g_K[BB*HH*SS*DK];
__device__ float g_V[BB*HH*SS*DK];
__device__ float g_ctx[BB*SS*DD];

// ---------------------------------------------------------------------------
// Tiled SGEMM with bias: C = A[M,K] @ W[K,N] + bias[N]
// BM=BN=64, BK=16, 256 threads, 4x4 per thread.
// SPLIT_HEADS: write C[m][n] to [B,H,S,dk] layout instead of row-major.
// ---------------------------------------------------------------------------
template<bool SPLIT_HEADS>
__global__ __launch_bounds__(256)
void gemm_bias_kernel(const float* __restrict__ A, const float* __restrict__ W,
                      const float* __restrict__ bias, float* __restrict__ C,
                      int M, int N, int K)
{
    __shared__ float As[16][68];   // transposed A tile, stride 68 (f4-aligned, conflict-light)
    __shared__ float Bs[16][64];

    const int tid = threadIdx.x;
    const int tx = tid & 15;       // 0..15
    const int ty = tid >> 4;       // 0..15
    const int m0 = blockIdx.y * 64;
    const int n0 = blockIdx.x * 64;

    // load mapping
    const int arow  = tid >> 2;          // 0..63
    const int acol4 = (tid & 3) << 2;    // 0,4,8,12
    const int brow  = tid >> 4;          // 0..15
    const int bcol4 = (tid & 15) << 2;   // 0..60

    float acc[4][4];
#pragma unroll
    for (int i = 0; i < 4; i++)
#pragma unroll
        for (int j = 0; j < 4; j++) acc[i][j] = 0.f;

    for (int k0 = 0; k0 < K; k0 += 16) {
        float4 a = *(const float4*)&A[(size_t)(m0 + arow) * K + k0 + acol4];
        As[acol4 + 0][arow] = a.x;
        As[acol4 + 1][arow] = a.y;
        As[acol4 + 2][arow] = a.z;
        As[acol4 + 3][arow] = a.w;
        float4 b = *(const float4*)&W[(size_t)(k0 + brow) * N + n0 + bcol4];
        *(float4*)&Bs[brow][bcol4] = b;
        __syncthreads();

#pragma unroll
        for (int kk = 0; kk < 16; kk++) {
            float4 ra = *(const float4*)&As[kk][ty << 2];
            float4 rb = *(const float4*)&Bs[kk][tx << 2];
            float a0 = ra.x, a1 = ra.y, a2 = ra.z, a3 = ra.w;
            float b0 = rb.x, b1 = rb.y, b2 = rb.z, b3 = rb.w;
            acc[0][0] += a0*b0; acc[0][1] += a0*b1; acc[0][2] += a0*b2; acc[0][3] += a0*b3;
            acc[1][0] += a1*b0; acc[1][1] += a1*b1; acc[1][2] += a1*b2; acc[1][3] += a1*b3;
            acc[2][0] += a2*b0; acc[2][1] += a2*b1; acc[2][2] += a2*b2; acc[2][3] += a2*b3;
            acc[3][0] += a3*b0; acc[3][1] += a3*b1; acc[3][2] += a3*b2; acc[3][3] += a3*b3;
        }
        __syncthreads();
    }

#pragma unroll
    for (int i = 0; i < 4; i++) {
        int m = m0 + (ty << 2) + i;
#pragma unroll
        for (int j = 0; j < 4; j++) {
            int n = n0 + (tx << 2) + j;
            float v = acc[i][j] + bias[n];
            if (SPLIT_HEADS) {
                // m = b*S + s ; n = h*DK + d -> [B,H,S,DK]
                int b = m >> 11, s = m & (SS - 1);
                int h = n >> 6, d = n & 63;
                C[(((size_t)(b * HH + h) * SS + s) << 6) + d] = v;
            } else {
                C[(size_t)m * N + n] = v;
            }
        }
    }
}

// ---------------------------------------------------------------------------
// Flash-style attention: one CTA = 64 query rows of one (b,h).
// 256 threads: thread -> (qr = tid/4, sub = tid%3..), owns 16 score cols
// (kc = sub + 4*i) and 16 output dims (d = sub*16 + c).
// ---------------------------------------------------------------------------
#define Q_STRIDE 68
#define K_STRIDE 68
#define V_STRIDE 64
#define P_STRIDE 65
#define SMEM_FLOATS (64*Q_STRIDE + 64*K_STRIDE + 64*V_STRIDE + 64*P_STRIDE)

__global__ __launch_bounds__(256)
void attn_kernel(const float* __restrict__ Q, const float* __restrict__ K,
                 const float* __restrict__ V, float* __restrict__ ctx)
{
    extern __shared__ float sm[];
    float* Qs = sm;                        // 64 x 68
    float* Ks = Qs + 64 * Q_STRIDE;        // 64 x 68
    float* Vs = Ks + 64 * K_STRIDE;        // 64 x 64
    float* Ps = Vs + 64 * V_STRIDE;        // 64 x 65

    const int tid = threadIdx.x;
    const int qr  = tid >> 2;    // 0..63
    const int sub = tid & 3;     // 0..3

    const int b = blockIdx.z;
    const int h = blockIdx.y;
    const int q0 = blockIdx.x * 64;
    const size_t head_off = (size_t)(b * HH + h) * SS * DK;

    const float* Qp = Q + head_off + (size_t)q0 * DK;
    const float* Kp = K + head_off;
    const float* Vp = V + head_off;

    // Load Q tile, fold in 1/sqrt(dk) = 1/8
    for (int idx = tid; idx < 64 * 64; idx += 256) {
        int r = idx >> 6, d = idx & 63;
        Qs[r * Q_STRIDE + d] = Qp[idx] * 0.125f;
    }
    __syncthreads();

    float mrow = -CUDART_INF_F;
    float lrow = 0.f;
    float acc[16];
#pragma unroll
    for (int c = 0; c < 16; c++) acc[c] = 0.f;

    for (int t = 0; t < SS / 64; ++t) {
        const float* Kt = Kp + (size_t)t * 64 * DK;
        const float* Vt = Vp + (size_t)t * 64 * DK;
        for (int idx = tid; idx < 64 * 64; idx += 256) {
            int r = idx >> 6, d = idx & 63;
            Ks[r * K_STRIDE + d] = Kt[idx];
            Vs[idx] = Vt[idx];               // stride 64 = natural
        }
        __syncthreads();

        // ---- scores: sc[i] = Q[qr] . K[sub + 4i]
        float sc[16];
#pragma unroll
        for (int i = 0; i < 16; i++) sc[i] = 0.f;
        const float4* Qr4 = (const float4*)(Qs + qr * Q_STRIDE);
#pragma unroll
        for (int d4 = 0; d4 < 16; ++d4) {
            float4 qv = Qr4[d4];
#pragma unroll
            for (int i = 0; i < 16; ++i) {
                const float4 kv = *(const float4*)(Ks + (sub + (i << 2)) * K_STRIDE + (d4 << 2));
                sc[i] += qv.x * kv.x + qv.y * kv.y + qv.z * kv.z + qv.w * kv.w;
            }
        }

        // ---- online softmax update (4 lanes per row cooperate via shfl)
        float tmax = sc[0];
#pragma unroll
        for (int i = 1; i < 16; i++) tmax = fmaxf(tmax, sc[i]);
        tmax = fmaxf(tmax, __shfl_xor_sync(0xffffffffu, tmax, 1));
        tmax = fmaxf(tmax, __shfl_xor_sync(0xffffffffu, tmax, 2));
        float mnew = fmaxf(mrow, tmax);
        float alpha = __expf(mrow - mnew);

        float psum = 0.f;
#pragma unroll
        for (int i = 0; i < 16; i++) {
            float p = __expf(sc[i] - mnew);
            psum += p;
            Ps[qr * P_STRIDE + sub + (i << 2)] = p;
        }
        psum += __shfl_xor_sync(0xffffffffu, psum, 1);
        psum += __shfl_xor_sync(0xffffffffu, psum, 2);
        lrow = lrow * alpha + psum;
        mrow = mnew;
#pragma unroll
        for (int c = 0; c < 16; c++) acc[c] *= alpha;
        __syncwarp();   // P row written by 4 lanes of the same warp

        // ---- acc += P[qr] @ V ; thread owns dims [sub*16 .. sub*16+15]
        const int dbase4 = sub << 2;   // float4 index into a 16-f4 row
#pragma unroll 8
        for (int k = 0; k < 64; ++k) {
            float pv = Ps[qr * P_STRIDE + k];
            const float4* Vr = (const float4*)(Vs + (k << 6)) + dbase4;
            float4 v0 = Vr[0], v1 = Vr[1], v2 = Vr[2], v3 = Vr[3];
            acc[0]  += pv * v0.x; acc[1]  += pv * v0.y; acc[2]  += pv * v0.z; acc[3]  += pv * v0.w;
            acc[4]  += pv * v1.x; acc[5]  += pv * v1.y; acc[6]  += pv * v1.z; acc[7]  += pv * v1.w;
            acc[8]  += pv * v2.x; acc[9]  += pv * v2.y; acc[10] += pv * v2.z; acc[11] += pv * v2.w;
            acc[12] += pv * v3.x; acc[13] += pv * v3.y; acc[14] += pv * v3.z; acc[15] += pv * v3.w;
        }
        __syncthreads();
    }

    // Epilogue: ctx[b][q0+qr][h*64 + sub*16 + c] = acc[c] / l
    float inv_l = 1.f / lrow;
    float* outp = ctx + ((size_t)(b * SS + q0 + qr)) * DD + h * 64 + sub * 16;
#pragma unroll
    for (int c4 = 0; c4 < 4; c4++) {
        float4 o;
        o.x = acc[c4*4+0] * inv_l;
        o.y = acc[c4*4+1] * inv_l;
        o.z = acc[c4*4+2] * inv_l;
        o.w = acc[c4*4+3] * inv_l;
        *(float4*)(outp + (c4 << 2)) = o;
    }
}

// ---------------------------------------------------------------------------
extern "C" void kernel_launch(void* const* d_in, const int* in_sizes, int n_in,
                              void* d_out, int out_size)
{
    const float* x  = (const float*)d_in[0];
    const float* Wq = (const float*)d_in[1];
    const float* bq = (const float*)d_in[2];
    const float* Wk = (const float*)d_in[3];
    const float* bk = (const float*)d_in[4];
    const float* Wv = (const float*)d_in[5];
    const float* bv = (const float*)d_in[6];
    const float* Wo = (const float*)d_in[7];
    const float* bo = (const float*)d_in[8];
    float* out = (float*)d_out;

    float *Qb, *Kb, *Vb, *Cb;
    cudaGetSymbolAddress((void**)&Qb, g_Q);
    cudaGetSymbolAddress((void**)&Kb, g_K);
    cudaGetSymbolAddress((void**)&Vb, g_V);
    cudaGetSymbolAddress((void**)&Cb, g_ctx);

    dim3 gemm_grid(DD / 64, MM / 64);   // (16, 128)

    gemm_bias_kernel<true><<<gemm_grid, 256>>>(x, Wq, bq, Qb, MM, DD, DD);
    gemm_bias_kernel<true><<<gemm_grid, 256>>>(x, Wk, bk, Kb, MM, DD, DD);
    gemm_bias_kernel<true><<<gemm_grid, 256>>>(x, Wv, bv, Vb, MM, DD, DD);

    const int smem_bytes = SMEM_FLOATS * sizeof(float);
    cudaFuncSetAttribute((const void*)attn_kernel,
                         cudaFuncAttributeMaxDynamicSharedMemorySize, smem_bytes);
    attn_kernel<<<dim3(SS / 64, HH, BB), 256, smem_bytes>>>(Qb, Kb, Vb, Cb);

    gemm_bias_kernel<false><<<gemm_grid, 256>>>(Cb, Wo, bo, out, MM, DD, DD);
}

// round 2
// speedup vs baseline: 3.2871x; 3.2871x over previous
#include <cuda_runtime.h>
#include <cuda_bf16.h>
#include <math_constants.h>

// Problem constants
#define BB 4
#define SS 2048
#define DD 1024
#define HH 16
#define DK 64
#define MM (BB*SS)          // 8192 rows

// Scratch in device globals (no allocation allowed)
__device__ float g_Q[BB*HH*SS*DK];
__device__ float g_K[BB*HH*SS*DK];
__device__ float g_V[BB*HH*SS*DK];
__device__ float g_ctx[BB*SS*DD];

// ---------------------------------------------------------------------------
// SGEMM v2: C = A[M,K] @ W[K,N] + bias[N]
// 128x128x16 tiles, 256 threads, 8x8 per thread, double-buffered smem.
// SPLIT_HEADS: write C[m][n] to [B,H,S,dk] layout.
// ---------------------------------------------------------------------------
template<bool SPLIT_HEADS>
__global__ __launch_bounds__(256)
void gemm128(const float* __restrict__ A, const float* __restrict__ W,
             const float* __restrict__ bias, float* __restrict__ C,
             int M, int N, int K)
{
    __shared__ float As[2][16][132];   // [buf][k][m], padded
    __shared__ float Bs[2][16][128];   // [buf][k][n]

    const int tid = threadIdx.x;
    const int tx = tid & 15;           // col group
    const int ty = tid >> 4;           // row group
    const int m0 = blockIdx.y * 128;
    const int n0 = blockIdx.x * 128;

    const int a_row  = tid >> 2;          // 0..63 (+64 for second)
    const int a_kc4  = (tid & 3) << 2;    // 0,4,8,12
    const int b_krow = tid >> 5;          // 0..7 (+8)
    const int b_nc4  = (tid & 31) << 2;   // 0..124

    const int nk = K / 16;

    float4 ra[2], rb[2];
#pragma unroll
    for (int i = 0; i < 2; i++) {
        ra[i] = *(const float4*)&A[(size_t)(m0 + a_row + 64*i) * K + a_kc4];
        rb[i] = *(const float4*)&W[(size_t)(b_krow + 8*i) * N + n0 + b_nc4];
    }
#pragma unroll
    for (int i = 0; i < 2; i++) {
        As[0][a_kc4+0][a_row+64*i] = ra[i].x;
        As[0][a_kc4+1][a_row+64*i] = ra[i].y;
        As[0][a_kc4+2][a_row+64*i] = ra[i].z;
        As[0][a_kc4+3][a_row+64*i] = ra[i].w;
        *(float4*)&Bs[0][b_krow+8*i][b_nc4] = rb[i];
    }
    __syncthreads();

    float acc[8][8];
#pragma unroll
    for (int i = 0; i < 8; i++)
#pragma unroll
        for (int j = 0; j < 8; j++) acc[i][j] = 0.f;

    int buf = 0;
    for (int kb = 0; kb < nk; ++kb) {
        if (kb + 1 < nk) {
            const int kof = (kb + 1) * 16;
#pragma unroll
            for (int i = 0; i < 2; i++) {
                ra[i] = *(const float4*)&A[(size_t)(m0 + a_row + 64*i) * K + kof + a_kc4];
                rb[i] = *(const float4*)&W[(size_t)(kof + b_krow + 8*i) * N + n0 + b_nc4];
            }
        }
#pragma unroll
        for (int kk = 0; kk < 16; ++kk) {
            float4 a0 = *(const float4*)&As[buf][kk][ty*4];
            float4 a1 = *(const float4*)&As[buf][kk][ty*4+64];
            float4 b0 = *(const float4*)&Bs[buf][kk][tx*4];
            float4 b1 = *(const float4*)&Bs[buf][kk][tx*4+64];
            float av[8] = {a0.x,a0.y,a0.z,a0.w,a1.x,a1.y,a1.z,a1.w};
            float bv[8] = {b0.x,b0.y,b0.z,b0.w,b1.x,b1.y,b1.z,b1.w};
#pragma unroll
            for (int i = 0; i < 8; i++)
#pragma unroll
                for (int j = 0; j < 8; j++)
                    acc[i][j] += av[i] * bv[j];
        }
        if (kb + 1 < nk) {
            buf ^= 1;
#pragma unroll
            for (int i = 0; i < 2; i++) {
                As[buf][a_kc4+0][a_row+64*i] = ra[i].x;
                As[buf][a_kc4+1][a_row+64*i] = ra[i].y;
                As[buf][a_kc4+2][a_row+64*i] = ra[i].z;
                As[buf][a_kc4+3][a_row+64*i] = ra[i].w;
                *(float4*)&Bs[buf][b_krow+8*i][b_nc4] = rb[i];
            }
            __syncthreads();
        }
    }

    // Epilogue
    float4 bia0 = *(const float4*)&bias[n0 + tx*4];
    float4 bia1 = *(const float4*)&bias[n0 + tx*4 + 64];
    float bv[8] = {bia0.x,bia0.y,bia0.z,bia0.w,bia1.x,bia1.y,bia1.z,bia1.w};

#pragma unroll
    for (int i = 0; i < 8; i++) {
        int m = m0 + ty*4 + (i & 3) + ((i >> 2) << 6);
#pragma unroll
        for (int jg = 0; jg < 2; jg++) {
            int n = n0 + tx*4 + (jg << 6);
            float4 o;
            o.x = acc[i][jg*4+0] + bv[jg*4+0];
            o.y = acc[i][jg*4+1] + bv[jg*4+1];
            o.z = acc[i][jg*4+2] + bv[jg*4+2];
            o.w = acc[i][jg*4+3] + bv[jg*4+3];
            if (SPLIT_HEADS) {
                int b = m >> 11, s = m & (SS - 1);
                int h = n >> 6, d = n & 63;
                *(float4*)&C[(((size_t)(b * HH + h) * SS + s) << 6) + d] = o;
            } else {
                *(float4*)&C[(size_t)m * N + n] = o;
            }
        }
    }
}

// ---------------------------------------------------------------------------
// Attention v2: one CTA = 64 q-rows of one (b,h). Outer-product tiling:
// 256 threads as 16x16; thread owns 4x4 of scores AND 4 rows x 4 dims of out.
// Softmax state replicated across the 16 lanes of each row-group (shfl).
// ---------------------------------------------------------------------------
#define QT_STRIDE 68
#define KT_STRIDE 68
#define P_STRIDE  68
#define ATT_SMEM_FLOATS (64*QT_STRIDE + 64*KT_STRIDE + 64*64 + 64*P_STRIDE)

__global__ __launch_bounds__(256)
void attn_kernel2(const float* __restrict__ Q, const float* __restrict__ K,
                  const float* __restrict__ V, float* __restrict__ ctx)
{
    extern __shared__ float sm[];
    float* QsT = sm;                        // [d][row]  64x68
    float* KsT = QsT + 64 * QT_STRIDE;      // [d][col]  64x68
    float* Vs  = KsT + 64 * KT_STRIDE;      // [k][dim]  64x64
    float* Ps  = Vs + 64 * 64;              // [row][col] 64x68

    const int tid = threadIdx.x;
    const int tx = tid & 15;   // score cols / out dims group
    const int ty = tid >> 4;   // q-row group

    const int b = blockIdx.z;
    const int h = blockIdx.y;
    const int q0 = blockIdx.x * 64;
    const size_t head_off = (size_t)(b * HH + h) * SS * DK;

    const float* Qp = Q + head_off + (size_t)q0 * DK;
    const float* Kp = K + head_off;
    const float* Vp = V + head_off;

    // Load Q tile transposed, fold in 1/sqrt(dk) = 1/8
#pragma unroll
    for (int i = 0; i < 4; i++) {
        int f4i = tid + (i << 8);           // 0..1023
        int row = f4i >> 4, d4 = (f4i & 15) << 2;
        float4 qv = *(const float4*)&Qp[(row << 6) + d4];
        QsT[(d4+0)*QT_STRIDE + row] = qv.x * 0.125f;
        QsT[(d4+1)*QT_STRIDE + row] = qv.y * 0.125f;
        QsT[(d4+2)*QT_STRIDE + row] = qv.z * 0.125f;
        QsT[(d4+3)*QT_STRIDE + row] = qv.w * 0.125f;
    }

    float m[4], l[4], acc[4][4];
#pragma unroll
    for (int i = 0; i < 4; i++) {
        m[i] = -CUDART_INF_F; l[i] = 0.f;
#pragma unroll
        for (int j = 0; j < 4; j++) acc[i][j] = 0.f;
    }

    for (int t = 0; t < SS / 64; ++t) {
        __syncthreads();   // prev PV done (and Q load on t=0)
        const float* Kt = Kp + ((size_t)t << 12);  // t*64*64
        const float* Vt = Vp + ((size_t)t << 12);
#pragma unroll
        for (int i = 0; i < 4; i++) {
            int f4i = tid + (i << 8);
            int row = f4i >> 4, d4 = (f4i & 15) << 2;
            float4 kv = *(const float4*)&Kt[(row << 6) + d4];
            KsT[(d4+0)*KT_STRIDE + row] = kv.x;
            KsT[(d4+1)*KT_STRIDE + row] = kv.y;
            KsT[(d4+2)*KT_STRIDE + row] = kv.z;
            KsT[(d4+3)*KT_STRIDE + row] = kv.w;
            *(float4*)&Vs[f4i << 2] = *(const float4*)&Vt[f4i << 2];
        }
        __syncthreads();

        // ---- scores 4x4 via outer product over d
        float sc[4][4];
#pragma unroll
        for (int i = 0; i < 4; i++)
#pragma unroll
            for (int j = 0; j < 4; j++) sc[i][j] = 0.f;
#pragma unroll 8
        for (int d = 0; d < 64; ++d) {
            float4 qv = *(const float4*)&QsT[d*QT_STRIDE + (ty<<2)];
            float4 kv = *(const float4*)&KsT[d*KT_STRIDE + (tx<<2)];
            float qa[4] = {qv.x,qv.y,qv.z,qv.w};
            float ka[4] = {kv.x,kv.y,kv.z,kv.w};
#pragma unroll
            for (int i = 0; i < 4; i++)
#pragma unroll
                for (int j = 0; j < 4; j++)
                    sc[i][j] += qa[i] * ka[j];
        }

        // ---- online softmax; row-group = 16 lanes sharing ty
#pragma unroll
        for (int i = 0; i < 4; i++) {
            float tm = fmaxf(fmaxf(sc[i][0], sc[i][1]), fmaxf(sc[i][2], sc[i][3]));
            tm = fmaxf(tm, __shfl_xor_sync(0xffffffffu, tm, 1));
            tm = fmaxf(tm, __shfl_xor_sync(0xffffffffu, tm, 2));
            tm = fmaxf(tm, __shfl_xor_sync(0xffffffffu, tm, 4));
            tm = fmaxf(tm, __shfl_xor_sync(0xffffffffu, tm, 8));
            float mnew = fmaxf(m[i], tm);
            float alpha = __expf(m[i] - mnew);
            float4 p;
            p.x = __expf(sc[i][0] - mnew);
            p.y = __expf(sc[i][1] - mnew);
            p.z = __expf(sc[i][2] - mnew);
            p.w = __expf(sc[i][3] - mnew);
            float ps = p.x + p.y + p.z + p.w;
            ps += __shfl_xor_sync(0xffffffffu, ps, 1);
            ps += __shfl_xor_sync(0xffffffffu, ps, 2);
            ps += __shfl_xor_sync(0xffffffffu, ps, 4);
            ps += __shfl_xor_sync(0xffffffffu, ps, 8);
            l[i] = l[i] * alpha + ps;
            m[i] = mnew;
            acc[i][0] *= alpha; acc[i][1] *= alpha;
            acc[i][2] *= alpha; acc[i][3] *= alpha;
            *(float4*)&Ps[((ty<<2)+i)*P_STRIDE + (tx<<2)] = p;
        }
        __syncthreads();

        // ---- acc += P @ V via outer product over k (unroll 4)
#pragma unroll 4
        for (int k4 = 0; k4 < 16; ++k4) {
            float4 pv[4];
#pragma unroll
            for (int i = 0; i < 4; i++)
                pv[i] = *(const float4*)&Ps[((ty<<2)+i)*P_STRIDE + (k4<<2)];
#pragma unroll
            for (int kk = 0; kk < 4; ++kk) {
                float4 vv = *(const float4*)&Vs[(((k4<<2)+kk) << 6) + (tx<<2)];
                float pk[4] = {
                    kk==0?pv[0].x:kk==1?pv[0].y:kk==2?pv[0].z:pv[0].w,
                    kk==0?pv[1].x:kk==1?pv[1].y:kk==2?pv[1].z:pv[1].w,
                    kk==0?pv[2].x:kk==1?pv[2].y:kk==2?pv[2].z:pv[2].w,
                    kk==0?pv[3].x:kk==1?pv[3].y:kk==2?pv[3].z:pv[3].w };
#pragma unroll
                for (int i = 0; i < 4; i++) {
                    acc[i][0] += pk[i] * vv.x;
                    acc[i][1] += pk[i] * vv.y;
                    acc[i][2] += pk[i] * vv.z;
                    acc[i][3] += pk[i] * vv.w;
                }
            }
        }
    }

    // Epilogue: ctx[b][q0+row][h*64 + tx*4 + j] = acc/l
#pragma unroll
    for (int i = 0; i < 4; i++) {
        float inv_l = 1.f / l[i];
        float4 o;
        o.x = acc[i][0] * inv_l;
        o.y = acc[i][1] * inv_l;
        o.z = acc[i][2] * inv_l;
        o.w = acc[i][3] * inv_l;
        float* outp = ctx + ((size_t)(b * SS + q0 + (ty<<2) + i)) * DD + h * 64 + (tx<<2);
        *(float4*)outp = o;
    }
}

// ---------------------------------------------------------------------------
extern "C" void kernel_launch(void* const* d_in, const int* in_sizes, int n_in,
                              void* d_out, int out_size)
{
    const float* x  = (const float*)d_in[0];
    const float* Wq = (const float*)d_in[1];
    const float* bq = (const float*)d_in[2];
    const float* Wk = (const float*)d_in[3];
    const float* bk = (const float*)d_in[4];
    const float* Wv = (const float*)d_in[5];
    const float* bv = (const float*)d_in[6];
    const float* Wo = (const float*)d_in[7];
    const float* bo = (const float*)d_in[8];
    float* out = (float*)d_out;

    float *Qb, *Kb, *Vb, *Cb;
    cudaGetSymbolAddress((void**)&Qb, g_Q);
    cudaGetSymbolAddress((void**)&Kb, g_K);
    cudaGetSymbolAddress((void**)&Vb, g_V);
    cudaGetSymbolAddress((void**)&Cb, g_ctx);

    dim3 gemm_grid(DD / 128, MM / 128);   // (8, 64)

    gemm128<true><<<gemm_grid, 256>>>(x, Wq, bq, Qb, MM, DD, DD);
    gemm128<true><<<gemm_grid, 256>>>(x, Wk, bk, Kb, MM, DD, DD);
    gemm128<true><<<gemm_grid, 256>>>(x, Wv, bv, Vb, MM, DD, DD);

    const int smem_bytes = ATT_SMEM_FLOATS * sizeof(float);
    cudaFuncSetAttribute((const void*)attn_kernel2,
                         cudaFuncAttributeMaxDynamicSharedMemorySize, smem_bytes);
    attn_kernel2<<<dim3(SS / 64, HH, BB), 256, smem_bytes>>>(Qb, Kb, Vb, Cb);

    gemm128<false><<<gemm_grid, 256>>>(Cb, Wo, bo, out, MM, DD, DD);
}

// round 3
// speedup vs baseline: 9.0368x; 2.7491x over previous
#include <cuda_runtime.h>
#include <cuda_bf16.h>
#include <math_constants.h>
#include <cstdint>

// Problem constants
#define BB 4
#define SS 2048
#define DD 1024
#define HH 16
#define DK 64
#define MM (BB*SS)          // 8192 rows

// Scratch in device globals (no allocation allowed)
__device__ float g_Q[BB*HH*SS*DK];
__device__ float g_K[BB*HH*SS*DK];
__device__ float g_V[BB*HH*SS*DK];
__device__ float g_ctx[BB*SS*DD];

// fp32 -> tf32 (round to nearest) : zero-mean quantization error
__device__ __forceinline__ uint32_t f2tf(float x) {
    uint32_t r;
    asm("cvt.rna.tf32.f32 %0, %1;" : "=r"(r) : "f"(x));
    return r;
}

__device__ __forceinline__ void mma_tf32(float& d0, float& d1, float& d2, float& d3,
                                         uint32_t a0, uint32_t a1, uint32_t a2, uint32_t a3,
                                         uint32_t b0, uint32_t b1) {
    asm volatile(
        "mma.sync.aligned.m16n8k8.row.col.f32.tf32.tf32.f32 "
        "{%0,%1,%2,%3}, {%4,%5,%6,%7}, {%8,%9}, {%0,%1,%2,%3};"
        : "+f"(d0), "+f"(d1), "+f"(d2), "+f"(d3)
        : "r"(a0), "r"(a1), "r"(a2), "r"(a3), "r"(b0), "r"(b1));
}

// ---------------------------------------------------------------------------
// TF32 tensor-core GEMM: C = A[M,K] @ W[K,N] + bias[N]
// 128x128x16 tiles, 256 thr = 8 warps (2m x 4n), warp tile 64x32,
// mma.m16n8k8: per warp 4 m-frags x 4 n-frags. Double-buffered smem.
// AsT[k][m] stride 140 (frag loads conflict-free), Bs[k][n] stride 136.
// ---------------------------------------------------------------------------
#define AST_S 140
#define BS_S  136

template<bool SPLIT_HEADS>
__global__ __launch_bounds__(256)
void gemm_tc(const float* __restrict__ A, const float* __restrict__ W,
             const float* __restrict__ bias, float* __restrict__ C,
             int M, int N, int K)
{
    __shared__ uint32_t AsT[2][16][AST_S];
    __shared__ uint32_t Bs[2][16][BS_S];

    const int tid  = threadIdx.x;
    const int lane = tid & 31;
    const int warp = tid >> 5;
    const int g    = lane >> 2;   // groupID
    const int t4   = lane & 3;    // threadID_in_group
    const int wm   = warp >> 2;   // 0..1
    const int wn   = warp & 3;    // 0..3

    const int m0 = blockIdx.y * 128;
    const int n0 = blockIdx.x * 128;

    const int a_row = tid >> 2;          // 0..63 (+64)
    const int a_k4  = (tid & 3) << 2;    // 0,4,8,12
    const int b_k   = tid >> 5;          // 0..7 (+8)
    const int b_n4  = (tid & 31) << 2;   // 0..124

    const int nk = K / 16;

    float4 ra[2], rb[2];
#pragma unroll
    for (int i = 0; i < 2; i++) {
        ra[i] = *(const float4*)&A[(size_t)(m0 + a_row + 64*i) * K + a_k4];
        rb[i] = *(const float4*)&W[(size_t)(b_k + 8*i) * N + n0 + b_n4];
    }
#pragma unroll
    for (int i = 0; i < 2; i++) {
        AsT[0][a_k4+0][a_row+64*i] = f2tf(ra[i].x);
        AsT[0][a_k4+1][a_row+64*i] = f2tf(ra[i].y);
        AsT[0][a_k4+2][a_row+64*i] = f2tf(ra[i].z);
        AsT[0][a_k4+3][a_row+64*i] = f2tf(ra[i].w);
        uint4 u = {f2tf(rb[i].x), f2tf(rb[i].y), f2tf(rb[i].z), f2tf(rb[i].w)};
        *(uint4*)&Bs[0][b_k+8*i][b_n4] = u;
    }
    __syncthreads();

    float acc[4][4][4];
#pragma unroll
    for (int mi = 0; mi < 4; mi++)
#pragma unroll
        for (int ni = 0; ni < 4; ni++)
#pragma unroll
            for (int r = 0; r < 4; r++) acc[mi][ni][r] = 0.f;

    int buf = 0;
    for (int kb = 0; kb < nk; ++kb) {
        if (kb + 1 < nk) {
            const int kof = (kb + 1) * 16;
#pragma unroll
            for (int i = 0; i < 2; i++) {
                ra[i] = *(const float4*)&A[(size_t)(m0 + a_row + 64*i) * K + kof + a_k4];
                rb[i] = *(const float4*)&W[(size_t)(kof + b_k + 8*i) * N + n0 + b_n4];
            }
        }
#pragma unroll
        for (int ks = 0; ks < 2; ++ks) {
            uint32_t au[4][4], bu[4][2];
#pragma unroll
            for (int mi = 0; mi < 4; mi++) {
                const int mbase = wm*64 + mi*16 + g;
                au[mi][0] = AsT[buf][ks*8 + t4    ][mbase];
                au[mi][1] = AsT[buf][ks*8 + t4    ][mbase + 8];
                au[mi][2] = AsT[buf][ks*8 + t4 + 4][mbase];
                au[mi][3] = AsT[buf][ks*8 + t4 + 4][mbase + 8];
            }
#pragma unroll
            for (int ni = 0; ni < 4; ni++) {
                const int nbase = wn*32 + ni*8 + g;
                bu[ni][0] = Bs[buf][ks*8 + t4    ][nbase];
                bu[ni][1] = Bs[buf][ks*8 + t4 + 4][nbase];
            }
#pragma unroll
            for (int mi = 0; mi < 4; mi++)
#pragma unroll
                for (int ni = 0; ni < 4; ni++)
                    mma_tf32(acc[mi][ni][0], acc[mi][ni][1], acc[mi][ni][2], acc[mi][ni][3],
                             au[mi][0], au[mi][1], au[mi][2], au[mi][3],
                             bu[ni][0], bu[ni][1]);
        }
        if (kb + 1 < nk) {
            buf ^= 1;
#pragma unroll
            for (int i = 0; i < 2; i++) {
                AsT[buf][a_k4+0][a_row+64*i] = f2tf(ra[i].x);
                AsT[buf][a_k4+1][a_row+64*i] = f2tf(ra[i].y);
                AsT[buf][a_k4+2][a_row+64*i] = f2tf(ra[i].z);
                AsT[buf][a_k4+3][a_row+64*i] = f2tf(ra[i].w);
                uint4 u = {f2tf(rb[i].x), f2tf(rb[i].y), f2tf(rb[i].z), f2tf(rb[i].w)};
                *(uint4*)&Bs[buf][b_k+8*i][b_n4] = u;
            }
            __syncthreads();
        }
    }

    // Epilogue: rows m0 + wm*64 + mi*16 + g (+8), cols n0 + wn*32 + ni*8 + 2*t4 (+1)
#pragma unroll
    for (int mi = 0; mi < 4; mi++) {
#pragma unroll
        for (int ni = 0; ni < 4; ni++) {
            const int n = n0 + wn*32 + ni*8 + 2*t4;
            float2 bia = *(const float2*)&bias[n];
#pragma unroll
            for (int rr = 0; rr < 2; rr++) {
                const int m = m0 + wm*64 + mi*16 + g + rr*8;
                float2 o;
                o.x = acc[mi][ni][rr*2+0] + bia.x;
                o.y = acc[mi][ni][rr*2+1] + bia.y;
                if (SPLIT_HEADS) {
                    int b = m >> 11, s = m & (SS - 1);
                    int h = n >> 6, d = n & 63;
                    *(float2*)&C[(((size_t)(b * HH + h) * SS + s) << 6) + d] = o;
                } else {
                    *(float2*)&C[(size_t)m * N + n] = o;
                }
            }
        }
    }
}

// ---------------------------------------------------------------------------
// TF32 tensor-core flash attention.
// CTA = 64 q-rows of one (b,h), 128 threads = 4 warps x 16 rows.
// Q persistent in registers as mma A-fragments. K/V tiles (64x64) in smem,
// stride 76 => conflict-free B-fragment loads for both QK^T and PV.
// S->P relayout via shfl (C-frag -> A-frag), no P smem.
// ---------------------------------------------------------------------------
#define KV_S 76

__global__ __launch_bounds__(128, 3)
void attn_tc(const float* __restrict__ Q, const float* __restrict__ K,
             const float* __restrict__ V, float* __restrict__ ctx)
{
    __shared__ uint32_t Ks[64][KV_S];
    __shared__ uint32_t Vs[64][KV_S];

    const int tid  = threadIdx.x;
    const int lane = tid & 31;
    const int w    = tid >> 5;     // warp 0..3 -> rows w*16..w*16+15
    const int g    = lane >> 2;
    const int t4   = lane & 3;

    const int b  = blockIdx.z;
    const int h  = blockIdx.y;
    const int q0 = blockIdx.x * 64;
    const size_t head_off = (size_t)(b * HH + h) * SS * DK;

    // ---- load Q fragments (persistent), fold in 1/sqrt(dk)=0.125
    uint32_t qa[8][4];
    {
        const float* Qb = Q + head_off + (size_t)(q0 + w*16) * DK;
#pragma unroll
        for (int ks = 0; ks < 8; ks++) {
            qa[ks][0] = f2tf(Qb[(size_t)g       * DK + ks*8 + t4    ] * 0.125f);
            qa[ks][1] = f2tf(Qb[(size_t)(g + 8) * DK + ks*8 + t4    ] * 0.125f);
            qa[ks][2] = f2tf(Qb[(size_t)g       * DK + ks*8 + t4 + 4] * 0.125f);
            qa[ks][3] = f2tf(Qb[(size_t)(g + 8) * DK + ks*8 + t4 + 4] * 0.125f);
        }
    }

    float o[8][4];
#pragma unroll
    for (int ni = 0; ni < 8; ni++)
#pragma unroll
        for (int r = 0; r < 4; r++) o[ni][r] = 0.f;
    float m0r = -CUDART_INF_F, m1r = -CUDART_INF_F;
    float l0 = 0.f, l1 = 0.f;

    const int s0l = (lane & ~3) | (t4 >> 1);   // shfl src for cols t4
    const int s1l = s0l + 2;                   // shfl src for cols t4+4

    for (int t = 0; t < SS / 64; ++t) {
        __syncthreads();
        const float* Kt = K + head_off + ((size_t)t << 12);
        const float* Vt = V + head_off + ((size_t)t << 12);
#pragma unroll
        for (int i = 0; i < 8; i++) {
            int f4i = tid + (i << 7);       // 0..1023
            int kv = f4i >> 4, d4 = (f4i & 15) << 2;
            float4 kf = *(const float4*)&Kt[(kv << 6) + d4];
            uint4 ku = {f2tf(kf.x), f2tf(kf.y), f2tf(kf.z), f2tf(kf.w)};
            *(uint4*)&Ks[kv][d4] = ku;
            float4 vf = *(const float4*)&Vt[(kv << 6) + d4];
            uint4 vu = {f2tf(vf.x), f2tf(vf.y), f2tf(vf.z), f2tf(vf.w)};
            *(uint4*)&Vs[kv][d4] = vu;
        }
        __syncthreads();

        // ---- S = Q @ K^T  (16 x 64 per warp), fp32 accum in C-frags
        float s[8][4];
#pragma unroll
        for (int ni = 0; ni < 8; ni++)
#pragma unroll
            for (int r = 0; r < 4; r++) s[ni][r] = 0.f;
#pragma unroll
        for (int ks = 0; ks < 8; ks++) {
#pragma unroll
            for (int ni = 0; ni < 8; ni++) {
                uint32_t b0 = Ks[ni*8 + g][ks*8 + t4];
                uint32_t b1 = Ks[ni*8 + g][ks*8 + t4 + 4];
                mma_tf32(s[ni][0], s[ni][1], s[ni][2], s[ni][3],
                         qa[ks][0], qa[ks][1], qa[ks][2], qa[ks][3], b0, b1);
            }
        }

        // ---- online softmax (rows r0 = g, r1 = g+8; quad = 4 lanes/row)
        float mx0 = -CUDART_INF_F, mx1 = -CUDART_INF_F;
#pragma unroll
        for (int ni = 0; ni < 8; ni++) {
            mx0 = fmaxf(mx0, fmaxf(s[ni][0], s[ni][1]));
            mx1 = fmaxf(mx1, fmaxf(s[ni][2], s[ni][3]));
        }
        mx0 = fmaxf(mx0, __shfl_xor_sync(0xffffffffu, mx0, 1));
        mx0 = fmaxf(mx0, __shfl_xor_sync(0xffffffffu, mx0, 2));
        mx1 = fmaxf(mx1, __shfl_xor_sync(0xffffffffu, mx1, 1));
        mx1 = fmaxf(mx1, __shfl_xor_sync(0xffffffffu, mx1, 2));

        float mn0 = fmaxf(m0r, mx0), mn1 = fmaxf(m1r, mx1);
        float alpha0 = __expf(m0r - mn0), alpha1 = __expf(m1r - mn1);
        m0r = mn0; m1r = mn1;

        float ps0 = 0.f, ps1 = 0.f;
#pragma unroll
        for (int ni = 0; ni < 8; ni++) {
            s[ni][0] = __expf(s[ni][0] - mn0);
            s[ni][1] = __expf(s[ni][1] - mn0);
            s[ni][2] = __expf(s[ni][2] - mn1);
            s[ni][3] = __expf(s[ni][3] - mn1);
            ps0 += s[ni][0] + s[ni][1];
            ps1 += s[ni][2] + s[ni][3];
        }
        ps0 += __shfl_xor_sync(0xffffffffu, ps0, 1);
        ps0 += __shfl_xor_sync(0xffffffffu, ps0, 2);
        ps1 += __shfl_xor_sync(0xffffffffu, ps1, 1);
        ps1 += __shfl_xor_sync(0xffffffffu, ps1, 2);
        l0 = l0 * alpha0 + ps0;
        l1 = l1 * alpha1 + ps1;
#pragma unroll
        for (int ni = 0; ni < 8; ni++) {
            o[ni][0] *= alpha0; o[ni][1] *= alpha0;
            o[ni][2] *= alpha1; o[ni][3] *= alpha1;
        }

        // ---- O += P @ V ; P relayout C-frag -> A-frag via shfl
#pragma unroll
        for (int ks = 0; ks < 8; ks++) {
            float v00 = __shfl_sync(0xffffffffu, s[ks][0], s0l);
            float v01 = __shfl_sync(0xffffffffu, s[ks][1], s0l);
            float a0f = (t4 & 1) ? v01 : v00;
            float v10 = __shfl_sync(0xffffffffu, s[ks][0], s1l);
            float v11 = __shfl_sync(0xffffffffu, s[ks][1], s1l);
            float a2f = (t4 & 1) ? v11 : v10;
            float w00 = __shfl_sync(0xffffffffu, s[ks][2], s0l);
            float w01 = __shfl_sync(0xffffffffu, s[ks][3], s0l);
            float a1f = (t4 & 1) ? w01 : w00;
            float w10 = __shfl_sync(0xffffffffu, s[ks][2], s1l);
            float w11 = __shfl_sync(0xffffffffu, s[ks][3], s1l);
            float a3f = (t4 & 1) ? w11 : w10;
            uint32_t pa0 = f2tf(a0f), pa1 = f2tf(a1f);
            uint32_t pa2 = f2tf(a2f), pa3 = f2tf(a3f);
#pragma unroll
            for (int ni = 0; ni < 8; ni++) {
                uint32_t b0 = Vs[ks*8 + t4    ][ni*8 + g];
                uint32_t b1 = Vs[ks*8 + t4 + 4][ni*8 + g];
                mma_tf32(o[ni][0], o[ni][1], o[ni][2], o[ni][3],
                         pa0, pa1, pa2, pa3, b0, b1);
            }
        }
    }

    // ---- epilogue: ctx[b][q][h*64 + d] = O / l
    float inv0 = 1.f / l0, inv1 = 1.f / l1;
    const int q_r0 = q0 + w*16 + g;
#pragma unroll
    for (int ni = 0; ni < 8; ni++) {
        const int d = h*64 + ni*8 + 2*t4;
        float2 o0 = {o[ni][0] * inv0, o[ni][1] * inv0};
        float2 o1 = {o[ni][2] * inv1, o[ni][3] * inv1};
        *(float2*)&ctx[(size_t)(b * SS + q_r0    ) * DD + d] = o0;
        *(float2*)&ctx[(size_t)(b * SS + q_r0 + 8) * DD + d] = o1;
    }
}

// ---------------------------------------------------------------------------
extern "C" void kernel_launch(void* const* d_in, const int* in_sizes, int n_in,
                              void* d_out, int out_size)
{
    const float* x  = (const float*)d_in[0];
    const float* Wq = (const float*)d_in[1];
    const float* bq = (const float*)d_in[2];
    const float* Wk = (const float*)d_in[3];
    const float* bk = (const float*)d_in[4];
    const float* Wv = (const float*)d_in[5];
    const float* bv = (const float*)d_in[6];
    const float* Wo = (const float*)d_in[7];
    const float* bo = (const float*)d_in[8];
    float* out = (float*)d_out;

    float *Qb, *Kb, *Vb, *Cb;
    cudaGetSymbolAddress((void**)&Qb, g_Q);
    cudaGetSymbolAddress((void**)&Kb, g_K);
    cudaGetSymbolAddress((void**)&Vb, g_V);
    cudaGetSymbolAddress((void**)&Cb, g_ctx);

    dim3 gemm_grid(DD / 128, MM / 128);   // (8, 64)

    gemm_tc<true><<<gemm_grid, 256>>>(x, Wq, bq, Qb, MM, DD, DD);
    gemm_tc<true><<<gemm_grid, 256>>>(x, Wk, bk, Kb, MM, DD, DD);
    gemm_tc<true><<<gemm_grid, 256>>>(x, Wv, bv, Vb, MM, DD, DD);

    attn_tc<<<dim3(SS / 64, HH, BB), 128>>>(Qb, Kb, Vb, Cb);

    gemm_tc<false><<<gemm_grid, 256>>>(Cb, Wo, bo, out, MM, DD, DD);
}

// round 4
// speedup vs baseline: 11.7632x; 1.3017x over previous
#include <cuda_runtime.h>
#include <cuda_bf16.h>
#include <math_constants.h>
#include <cstdint>

// Problem constants
#define BB 4
#define SS 2048
#define DD 1024
#define HH 16
#define DK 64
#define MM (BB*SS)          // 8192 rows
#define KDIM 1024

// Scratch in device globals (no allocation allowed)
__device__ float g_xT[MM*DD];        // tf32-rounded x
__device__ float g_Wt[4][DD*DD];     // tf32-rounded Wq,Wk,Wv,Wo
__device__ float g_Q[BB*HH*SS*DK];
__device__ float g_K[BB*HH*SS*DK];
__device__ float g_V[BB*HH*SS*DK];
__device__ float g_ctx[BB*SS*DD];

// fp32 -> tf32 (round to nearest) kept in a float container
__device__ __forceinline__ float f2tf_f(float x) {
    uint32_t r;
    asm("cvt.rna.tf32.f32 %0, %1;" : "=r"(r) : "f"(x));
    return __uint_as_float(r);
}

__device__ __forceinline__ void mma_tf32(float& d0, float& d1, float& d2, float& d3,
                                         uint32_t a0, uint32_t a1, uint32_t a2, uint32_t a3,
                                         uint32_t b0, uint32_t b1) {
    asm volatile(
        "mma.sync.aligned.m16n8k8.row.col.f32.tf32.tf32.f32 "
        "{%0,%1,%2,%3}, {%4,%5,%6,%7}, {%8,%9}, {%0,%1,%2,%3};"
        : "+f"(d0), "+f"(d1), "+f"(d2), "+f"(d3)
        : "r"(a0), "r"(a1), "r"(a2), "r"(a3), "r"(b0), "r"(b1));
}

__device__ __forceinline__ void cp_async16(uint32_t dst, const void* src) {
    asm volatile("cp.async.cg.shared.global [%0], [%1], 16;" :: "r"(dst), "l"(src));
}
#define CP_COMMIT() asm volatile("cp.async.commit_group;")

// ---------------------------------------------------------------------------
// Pre-convert fp32 -> tf32-rounded fp32 (vectorized)
// ---------------------------------------------------------------------------
__global__ __launch_bounds__(256)
void tf32ify(const float4* __restrict__ in, float4* __restrict__ out, int n4)
{
    int i = blockIdx.x * 256 + threadIdx.x;
    if (i < n4) {
        float4 v = in[i];
        v.x = f2tf_f(v.x); v.y = f2tf_f(v.y);
        v.z = f2tf_f(v.z); v.w = f2tf_f(v.w);
        out[i] = v;
    }
}

// ---------------------------------------------------------------------------
// TF32 tensor-core GEMM, cp.async 3-stage pipeline.
// C = A[M,1024] @ W[1024,1024] + bias. 128x128x16 tiles, 8 warps (2m x 4n),
// warp tile 64x32, mma.m16n8k8. A row-major smem stride 20 (conflict-free),
// B row-major stride 136 (conflict-free). A, W are pre-tf32-rounded.
// ---------------------------------------------------------------------------
#define SA 20
#define SB 136
#define A_ST (128*SA)          // 2560 words
#define G_STAGE (A_ST + 16*SB) // 4736 words
#define GEMM_SMEM (3*G_STAGE*4)

template<bool SPLIT_HEADS>
__global__ __launch_bounds__(256, 2)
void gemm_tc3(const float* __restrict__ A, const float* __restrict__ W,
              const float* __restrict__ bias, float* __restrict__ C)
{
    extern __shared__ float smemf[];
    const uint32_t smem_u32 = (uint32_t)__cvta_generic_to_shared(smemf);
    const uint32_t* smu = (const uint32_t*)smemf;

    const int tid  = threadIdx.x;
    const int lane = tid & 31;
    const int warp = tid >> 5;
    const int g    = lane >> 2;
    const int t4   = lane & 3;
    const int wm   = warp >> 2;   // 0..1
    const int wn   = warp & 3;    // 0..3

    const int m0 = blockIdx.y * 128;
    const int n0 = blockIdx.x * 128;
    const int nk = KDIM / 16;     // 64

    auto issue = [&](int kb, int stg) {
        const int base = stg * G_STAGE;
#pragma unroll
        for (int i = 0; i < 2; i++) {
            int c = tid + i*256;
            int m = c >> 2, k4 = (c & 3) << 2;
            cp_async16(smem_u32 + (base + m*SA + k4)*4,
                       A + (size_t)(m0 + m)*KDIM + kb*16 + k4);
        }
#pragma unroll
        for (int i = 0; i < 2; i++) {
            int c = tid + i*256;
            int kr = c >> 5, n4 = (c & 31) << 2;
            cp_async16(smem_u32 + (base + A_ST + kr*SB + n4)*4,
                       W + (size_t)(kb*16 + kr)*DD + n0 + n4);
        }
        CP_COMMIT();
    };

    issue(0, 0);
    issue(1, 1);

    float acc[4][4][4];
#pragma unroll
    for (int mi = 0; mi < 4; mi++)
#pragma unroll
        for (int ni = 0; ni < 4; ni++)
#pragma unroll
            for (int r = 0; r < 4; r++) acc[mi][ni][r] = 0.f;

    for (int kb = 0; kb < nk; ++kb) {
        if (kb + 2 < nk) asm volatile("cp.async.wait_group 1;");
        else             asm volatile("cp.async.wait_group 0;");
        __syncthreads();
        if (kb + 2 < nk) issue(kb + 2, (kb + 2) % 3);

        const int base = (kb % 3) * G_STAGE;
        const uint32_t* As = smu + base;
        const uint32_t* Bs = smu + base + A_ST;

#pragma unroll
        for (int ks = 0; ks < 2; ++ks) {
            uint32_t au[4][4], bu[4][2];
#pragma unroll
            for (int mi = 0; mi < 4; mi++) {
                const uint32_t* ap = As + (wm*64 + mi*16 + g)*SA + ks*8 + t4;
                au[mi][0] = ap[0];
                au[mi][1] = ap[8*SA];
                au[mi][2] = ap[4];
                au[mi][3] = ap[8*SA + 4];
            }
#pragma unroll
            for (int ni = 0; ni < 4; ni++) {
                const uint32_t* bp = Bs + (ks*8 + t4)*SB + wn*32 + ni*8 + g;
                bu[ni][0] = bp[0];
                bu[ni][1] = bp[4*SB];
            }
#pragma unroll
            for (int mi = 0; mi < 4; mi++)
#pragma unroll
                for (int ni = 0; ni < 4; ni++)
                    mma_tf32(acc[mi][ni][0], acc[mi][ni][1], acc[mi][ni][2], acc[mi][ni][3],
                             au[mi][0], au[mi][1], au[mi][2], au[mi][3],
                             bu[ni][0], bu[ni][1]);
        }
    }

    // Epilogue
#pragma unroll
    for (int mi = 0; mi < 4; mi++) {
#pragma unroll
        for (int ni = 0; ni < 4; ni++) {
            const int n = n0 + wn*32 + ni*8 + 2*t4;
            float2 bia = *(const float2*)&bias[n];
#pragma unroll
            for (int rr = 0; rr < 2; rr++) {
                const int m = m0 + wm*64 + mi*16 + g + rr*8;
                float2 o;
                o.x = acc[mi][ni][rr*2+0] + bia.x;
                o.y = acc[mi][ni][rr*2+1] + bia.y;
                if (SPLIT_HEADS) {
                    o.x = f2tf_f(o.x); o.y = f2tf_f(o.y);   // pre-round for attn
                    int b = m >> 11, s = m & (SS - 1);
                    int h = n >> 6, d = n & 63;
                    *(float2*)&C[(((size_t)(b * HH + h) * SS + s) << 6) + d] = o;
                } else {
                    *(float2*)&C[(size_t)m * DD + n] = o;
                }
            }
        }
    }
}

// ---------------------------------------------------------------------------
// TF32 tensor-core flash attention, cp.async double-buffered K/V.
// CTA = 64 q-rows of one (b,h), 4 warps x 16 rows. Q persistent in regs
// (raw bits, inputs pre-rounded). K stride 68, V stride 72 (conflict-free).
// S->P relayout via shfl. One barrier per KV tile.
// ---------------------------------------------------------------------------
#define KS_S 68
#define VS_S 72
#define ATT_STAGE (64*KS_S + 64*VS_S)   // 8960 words
#define ATT_SMEM (2*ATT_STAGE*4)

__global__ __launch_bounds__(128, 3)
void attn_tc3(const float* __restrict__ Q, const float* __restrict__ K,
              const float* __restrict__ V, float* __restrict__ ctx)
{
    extern __shared__ uint32_t smu[];
    const uint32_t smem_u32 = (uint32_t)__cvta_generic_to_shared(smu);

    const int tid  = threadIdx.x;
    const int lane = tid & 31;
    const int w    = tid >> 5;
    const int g    = lane >> 2;
    const int t4   = lane & 3;

    const int b  = blockIdx.z;
    const int h  = blockIdx.y;
    const int q0 = blockIdx.x * 64;
    const size_t head_off = (size_t)(b * HH + h) * SS * DK;

    auto issueKV = [&](int t, int stg) {
        const float* Kt = K + head_off + ((size_t)t << 12);
        const float* Vt = V + head_off + ((size_t)t << 12);
        const int base = stg * ATT_STAGE;
#pragma unroll
        for (int i = 0; i < 8; i++) {
            int c = tid + (i << 7);
            int kv = c >> 4, d4 = (c & 15) << 2;
            cp_async16(smem_u32 + (base + kv*KS_S + d4)*4, Kt + (kv << 6) + d4);
            cp_async16(smem_u32 + (base + 64*KS_S + kv*VS_S + d4)*4, Vt + (kv << 6) + d4);
        }
        CP_COMMIT();
    };

    issueKV(0, 0);

    // ---- Q fragments, raw bits (pre-rounded), fold 1/8 (exact pow2)
    uint32_t qa[8][4];
    {
        const float* Qb = Q + head_off + (size_t)(q0 + w*16) * DK;
#pragma unroll
        for (int ks = 0; ks < 8; ks++) {
            qa[ks][0] = __float_as_uint(Qb[(size_t)g       * DK + ks*8 + t4    ] * 0.125f);
            qa[ks][1] = __float_as_uint(Qb[(size_t)(g + 8) * DK + ks*8 + t4    ] * 0.125f);
            qa[ks][2] = __float_as_uint(Qb[(size_t)g       * DK + ks*8 + t4 + 4] * 0.125f);
            qa[ks][3] = __float_as_uint(Qb[(size_t)(g + 8) * DK + ks*8 + t4 + 4] * 0.125f);
        }
    }

    float o[8][4];
#pragma unroll
    for (int ni = 0; ni < 8; ni++)
#pragma unroll
        for (int r = 0; r < 4; r++) o[ni][r] = 0.f;
    float m0r = -CUDART_INF_F, m1r = -CUDART_INF_F;
    float l0 = 0.f, l1 = 0.f;

    const int s0l = (lane & ~3) | (t4 >> 1);
    const int s1l = s0l + 2;

    for (int t = 0; t < SS / 64; ++t) {
        asm volatile("cp.async.wait_group 0;");
        __syncthreads();
        if (t + 1 < SS / 64) issueKV(t + 1, (t + 1) & 1);

        const uint32_t* Kst = smu + (t & 1) * ATT_STAGE;
        const uint32_t* Vst = Kst + 64*KS_S;

        // ---- S = Q @ K^T
        float s[8][4];
#pragma unroll
        for (int ni = 0; ni < 8; ni++)
#pragma unroll
            for (int r = 0; r < 4; r++) s[ni][r] = 0.f;
#pragma unroll
        for (int ks = 0; ks < 8; ks++) {
#pragma unroll
            for (int ni = 0; ni < 8; ni++) {
                const uint32_t* kp = Kst + (ni*8 + g)*KS_S + ks*8 + t4;
                mma_tf32(s[ni][0], s[ni][1], s[ni][2], s[ni][3],
                         qa[ks][0], qa[ks][1], qa[ks][2], qa[ks][3], kp[0], kp[4]);
            }
        }

        // ---- online softmax (rows g, g+8; quad reduction)
        float mx0 = -CUDART_INF_F, mx1 = -CUDART_INF_F;
#pragma unroll
        for (int ni = 0; ni < 8; ni++) {
            mx0 = fmaxf(mx0, fmaxf(s[ni][0], s[ni][1]));
            mx1 = fmaxf(mx1, fmaxf(s[ni][2], s[ni][3]));
        }
        mx0 = fmaxf(mx0, __shfl_xor_sync(0xffffffffu, mx0, 1));
        mx0 = fmaxf(mx0, __shfl_xor_sync(0xffffffffu, mx0, 2));
        mx1 = fmaxf(mx1, __shfl_xor_sync(0xffffffffu, mx1, 1));
        mx1 = fmaxf(mx1, __shfl_xor_sync(0xffffffffu, mx1, 2));

        float mn0 = fmaxf(m0r, mx0), mn1 = fmaxf(m1r, mx1);
        float alpha0 = __expf(m0r - mn0), alpha1 = __expf(m1r - mn1);
        m0r = mn0; m1r = mn1;

        float ps0 = 0.f, ps1 = 0.f;
#pragma unroll
        for (int ni = 0; ni < 8; ni++) {
            s[ni][0] = __expf(s[ni][0] - mn0);
            s[ni][1] = __expf(s[ni][1] - mn0);
            s[ni][2] = __expf(s[ni][2] - mn1);
            s[ni][3] = __expf(s[ni][3] - mn1);
            ps0 += s[ni][0] + s[ni][1];
            ps1 += s[ni][2] + s[ni][3];
        }
        ps0 += __shfl_xor_sync(0xffffffffu, ps0, 1);
        ps0 += __shfl_xor_sync(0xffffffffu, ps0, 2);
        ps1 += __shfl_xor_sync(0xffffffffu, ps1, 1);
        ps1 += __shfl_xor_sync(0xffffffffu, ps1, 2);
        l0 = l0 * alpha0 + ps0;
        l1 = l1 * alpha1 + ps1;
#pragma unroll
        for (int ni = 0; ni < 8; ni++) {
            o[ni][0] *= alpha0; o[ni][1] *= alpha0;
            o[ni][2] *= alpha1; o[ni][3] *= alpha1;
        }

        // ---- O += P @ V ; C-frag -> A-frag via shfl
#pragma unroll
        for (int ks = 0; ks < 8; ks++) {
            float v00 = __shfl_sync(0xffffffffu, s[ks][0], s0l);
            float v01 = __shfl_sync(0xffffffffu, s[ks][1], s0l);
            float a0f = (t4 & 1) ? v01 : v00;
            float v10 = __shfl_sync(0xffffffffu, s[ks][0], s1l);
            float v11 = __shfl_sync(0xffffffffu, s[ks][1], s1l);
            float a2f = (t4 & 1) ? v11 : v10;
            float w00 = __shfl_sync(0xffffffffu, s[ks][2], s0l);
            float w01 = __shfl_sync(0xffffffffu, s[ks][3], s0l);
            float a1f = (t4 & 1) ? w01 : w00;
            float w10 = __shfl_sync(0xffffffffu, s[ks][2], s1l);
            float w11 = __shfl_sync(0xffffffffu, s[ks][3], s1l);
            float a3f = (t4 & 1) ? w11 : w10;
            uint32_t pa0 = __float_as_uint(f2tf_f(a0f));
            uint32_t pa1 = __float_as_uint(f2tf_f(a1f));
            uint32_t pa2 = __float_as_uint(f2tf_f(a2f));
            uint32_t pa3 = __float_as_uint(f2tf_f(a3f));
#pragma unroll
            for (int ni = 0; ni < 8; ni++) {
                const uint32_t* vp = Vst + (ks*8 + t4)*VS_S + ni*8 + g;
                mma_tf32(o[ni][0], o[ni][1], o[ni][2], o[ni][3],
                         pa0, pa1, pa2, pa3, vp[0], vp[4*VS_S]);
            }
        }
    }

    // ---- epilogue: ctx = O / l, rounded to tf32 for the Wo GEMM
    float inv0 = 1.f / l0, inv1 = 1.f / l1;
    const int q_r0 = q0 + w*16 + g;
#pragma unroll
    for (int ni = 0; ni < 8; ni++) {
        const int d = h*64 + ni*8 + 2*t4;
        float2 o0 = {f2tf_f(o[ni][0] * inv0), f2tf_f(o[ni][1] * inv0)};
        float2 o1 = {f2tf_f(o[ni][2] * inv1), f2tf_f(o[ni][3] * inv1)};
        *(float2*)&ctx[(size_t)(b * SS + q_r0    ) * DD + d] = o0;
        *(float2*)&ctx[(size_t)(b * SS + q_r0 + 8) * DD + d] = o1;
    }
}

// ---------------------------------------------------------------------------
extern "C" void kernel_launch(void* const* d_in, const int* in_sizes, int n_in,
                              void* d_out, int out_size)
{
    const float* x  = (const float*)d_in[0];
    const float* Wq = (const float*)d_in[1];
    const float* bq = (const float*)d_in[2];
    const float* Wk = (const float*)d_in[3];
    const float* bk = (const float*)d_in[4];
    const float* Wv = (const float*)d_in[5];
    const float* bv = (const float*)d_in[6];
    const float* Wo = (const float*)d_in[7];
    const float* bo = (const float*)d_in[8];
    float* out = (float*)d_out;

    float *xT, *Wt, *Qb, *Kb, *Vb, *Cb;
    cudaGetSymbolAddress((void**)&xT, g_xT);
    cudaGetSymbolAddress((void**)&Wt, g_Wt);
    cudaGetSymbolAddress((void**)&Qb, g_Q);
    cudaGetSymbolAddress((void**)&Kb, g_K);
    cudaGetSymbolAddress((void**)&Vb, g_V);
    cudaGetSymbolAddress((void**)&Cb, g_ctx);
    float* Wt0 = Wt;
    float* Wt1 = Wt + (size_t)DD*DD;
    float* Wt2 = Wt + 2*(size_t)DD*DD;
    float* Wt3 = Wt + 3*(size_t)DD*DD;

    // Pre-round inputs to tf32
    const int xn4 = MM*DD/4, wn4 = DD*DD/4;
    tf32ify<<<(xn4+255)/256, 256>>>((const float4*)x,  (float4*)xT,  xn4);
    tf32ify<<<(wn4+255)/256, 256>>>((const float4*)Wq, (float4*)Wt0, wn4);
    tf32ify<<<(wn4+255)/256, 256>>>((const float4*)Wk, (float4*)Wt1, wn4);
    tf32ify<<<(wn4+255)/256, 256>>>((const float4*)Wv, (float4*)Wt2, wn4);
    tf32ify<<<(wn4+255)/256, 256>>>((const float4*)Wo, (float4*)Wt3, wn4);

    dim3 gemm_grid(DD / 128, MM / 128);   // (8, 64)

    cudaFuncSetAttribute((const void*)gemm_tc3<true>,
                         cudaFuncAttributeMaxDynamicSharedMemorySize, GEMM_SMEM);
    cudaFuncSetAttribute((const void*)gemm_tc3<false>,
                         cudaFuncAttributeMaxDynamicSharedMemorySize, GEMM_SMEM);
    cudaFuncSetAttribute((const void*)attn_tc3,
                         cudaFuncAttributeMaxDynamicSharedMemorySize, ATT_SMEM);

    gemm_tc3<true><<<gemm_grid, 256, GEMM_SMEM>>>(xT, Wt0, bq, Qb);
    gemm_tc3<true><<<gemm_grid, 256, GEMM_SMEM>>>(xT, Wt1, bk, Kb);
    gemm_tc3<true><<<gemm_grid, 256, GEMM_SMEM>>>(xT, Wt2, bv, Vb);

    attn_tc3<<<dim3(SS / 64, HH, BB), 128, ATT_SMEM>>>(Qb, Kb, Vb, Cb);

    gemm_tc3<false><<<gemm_grid, 256, GEMM_SMEM>>>(Cb, Wt3, bo, out);
}

// round 5
// speedup vs baseline: 13.0079x; 1.1058x over previous
#include <cuda_runtime.h>
#include <cuda_bf16.h>
#include <math_constants.h>
#include <cstdint>

// Problem constants
#define BB 4
#define SS 2048
#define DD 1024
#define HH 16
#define DK 64
#define MM (BB*SS)          // 8192 rows
#define KDIM 1024

// Scratch in device globals (no allocation allowed)
__device__ float g_xT[MM*DD];        // tf32-rounded x
__device__ float g_Wt[4][DD*DD];     // tf32-rounded Wq,Wk,Wv,Wo
__device__ float g_Q[BB*HH*SS*DK];
__device__ float g_K[BB*HH*SS*DK];
__device__ float g_V[BB*HH*SS*DK];
__device__ float g_ctx[BB*SS*DD];

// fp32 -> tf32 (round to nearest) kept in a float container
__device__ __forceinline__ float f2tf_f(float x) {
    uint32_t r;
    asm("cvt.rna.tf32.f32 %0, %1;" : "=r"(r) : "f"(x));
    return __uint_as_float(r);
}

__device__ __forceinline__ void mma_tf32(float& d0, float& d1, float& d2, float& d3,
                                         uint32_t a0, uint32_t a1, uint32_t a2, uint32_t a3,
                                         uint32_t b0, uint32_t b1) {
    asm volatile(
        "mma.sync.aligned.m16n8k8.row.col.f32.tf32.tf32.f32 "
        "{%0,%1,%2,%3}, {%4,%5,%6,%7}, {%8,%9}, {%0,%1,%2,%3};"
        : "+f"(d0), "+f"(d1), "+f"(d2), "+f"(d3)
        : "r"(a0), "r"(a1), "r"(a2), "r"(a3), "r"(b0), "r"(b1));
}

__device__ __forceinline__ void cp_async16(uint32_t dst, const void* src) {
    asm volatile("cp.async.cg.shared.global [%0], [%1], 16;" :: "r"(dst), "l"(src));
}
#define CP_COMMIT() asm volatile("cp.async.commit_group;")

// ---------------------------------------------------------------------------
// Pre-convert fp32 -> tf32-rounded fp32 (vectorized)
// ---------------------------------------------------------------------------
__global__ __launch_bounds__(256)
void tf32ify(const float4* __restrict__ in, float4* __restrict__ out, int n4)
{
    int i = blockIdx.x * 256 + threadIdx.x;
    if (i < n4) {
        float4 v = in[i];
        v.x = f2tf_f(v.x); v.y = f2tf_f(v.y);
        v.z = f2tf_f(v.z); v.w = f2tf_f(v.w);
        out[i] = v;
    }
}

// ---------------------------------------------------------------------------
// TF32 tensor-core GEMM, cp.async 3-stage pipeline.
// C = A[M,1024] @ W[1024,1024] + bias. 128x128x16 tiles, 8 warps (2m x 4n),
// warp tile 64x32, mma.m16n8k8. A row-major smem stride 20 (conflict-free),
// B row-major stride 136 (conflict-free). A, W are pre-tf32-rounded.
// ---------------------------------------------------------------------------
#define SA 20
#define SB 136
#define A_ST (128*SA)          // 2560 words
#define G_STAGE (A_ST + 16*SB) // 4736 words
#define GEMM_SMEM (3*G_STAGE*4)

template<bool SPLIT_HEADS>
__global__ __launch_bounds__(256, 2)
void gemm_tc3(const float* __restrict__ A, const float* __restrict__ W,
              const float* __restrict__ bias, float* __restrict__ C)
{
    extern __shared__ float smemf[];
    const uint32_t smem_u32 = (uint32_t)__cvta_generic_to_shared(smemf);
    const uint32_t* smu = (const uint32_t*)smemf;

    const int tid  = threadIdx.x;
    const int lane = tid & 31;
    const int warp = tid >> 5;
    const int g    = lane >> 2;
    const int t4   = lane & 3;
    const int wm   = warp >> 2;   // 0..1
    const int wn   = warp & 3;    // 0..3

    const int m0 = blockIdx.y * 128;
    const int n0 = blockIdx.x * 128;
    const int nk = KDIM / 16;     // 64

    auto issue = [&](int kb, int stg) {
        const int base = stg * G_STAGE;
#pragma unroll
        for (int i = 0; i < 2; i++) {
            int c = tid + i*256;
            int m = c >> 2, k4 = (c & 3) << 2;
            cp_async16(smem_u32 + (base + m*SA + k4)*4,
                       A + (size_t)(m0 + m)*KDIM + kb*16 + k4);
        }
#pragma unroll
        for (int i = 0; i < 2; i++) {
            int c = tid + i*256;
            int kr = c >> 5, n4 = (c & 31) << 2;
            cp_async16(smem_u32 + (base + A_ST + kr*SB + n4)*4,
                       W + (size_t)(kb*16 + kr)*DD + n0 + n4);
        }
        CP_COMMIT();
    };

    issue(0, 0);
    issue(1, 1);

    float acc[4][4][4];
#pragma unroll
    for (int mi = 0; mi < 4; mi++)
#pragma unroll
        for (int ni = 0; ni < 4; ni++)
#pragma unroll
            for (int r = 0; r < 4; r++) acc[mi][ni][r] = 0.f;

    for (int kb = 0; kb < nk; ++kb) {
        if (kb + 2 < nk) asm volatile("cp.async.wait_group 1;");
        else             asm volatile("cp.async.wait_group 0;");
        __syncthreads();
        if (kb + 2 < nk) issue(kb + 2, (kb + 2) % 3);

        const int base = (kb % 3) * G_STAGE;
        const uint32_t* As = smu + base;
        const uint32_t* Bs = smu + base + A_ST;

#pragma unroll
        for (int ks = 0; ks < 2; ++ks) {
            uint32_t au[4][4], bu[4][2];
#pragma unroll
            for (int mi = 0; mi < 4; mi++) {
                const uint32_t* ap = As + (wm*64 + mi*16 + g)*SA + ks*8 + t4;
                au[mi][0] = ap[0];
                au[mi][1] = ap[8*SA];
                au[mi][2] = ap[4];
                au[mi][3] = ap[8*SA + 4];
            }
#pragma unroll
            for (int ni = 0; ni < 4; ni++) {
                const uint32_t* bp = Bs + (ks*8 + t4)*SB + wn*32 + ni*8 + g;
                bu[ni][0] = bp[0];
                bu[ni][1] = bp[4*SB];
            }
#pragma unroll
            for (int mi = 0; mi < 4; mi++)
#pragma unroll
                for (int ni = 0; ni < 4; ni++)
                    mma_tf32(acc[mi][ni][0], acc[mi][ni][1], acc[mi][ni][2], acc[mi][ni][3],
                             au[mi][0], au[mi][1], au[mi][2], au[mi][3],
                             bu[ni][0], bu[ni][1]);
        }
    }

    // Epilogue
#pragma unroll
    for (int mi = 0; mi < 4; mi++) {
#pragma unroll
        for (int ni = 0; ni < 4; ni++) {
            const int n = n0 + wn*32 + ni*8 + 2*t4;
            float2 bia = *(const float2*)&bias[n];
#pragma unroll
            for (int rr = 0; rr < 2; rr++) {
                const int m = m0 + wm*64 + mi*16 + g + rr*8;
                float2 o;
                o.x = acc[mi][ni][rr*2+0] + bia.x;
                o.y = acc[mi][ni][rr*2+1] + bia.y;
                if (SPLIT_HEADS) {
                    o.x = f2tf_f(o.x); o.y = f2tf_f(o.y);   // pre-round for attn
                    int b = m >> 11, s = m & (SS - 1);
                    int h = n >> 6, d = n & 63;
                    *(float2*)&C[(((size_t)(b * HH + h) * SS + s) << 6) + d] = o;
                } else {
                    *(float2*)&C[(size_t)m * DD + n] = o;
                }
            }
        }
    }
}

// ---------------------------------------------------------------------------
// TF32 tensor-core flash attention, mi=2: 32 q-rows per warp, 128 per CTA.
// Each K/V fragment load feeds 2 MMAs -> LDS bytes per output halved.
// K stride 68, V stride 72 (conflict-free). cp.async double-buffered KV.
// S->P relayout via shfl. One barrier per KV tile.
// ---------------------------------------------------------------------------
#define KS_S 68
#define VS_S 72
#define ATT_STAGE (64*KS_S + 64*VS_S)   // 8960 words
#define ATT_SMEM (2*ATT_STAGE*4)

__global__ __launch_bounds__(128, 2)
void attn_tc4(const float* __restrict__ Q, const float* __restrict__ K,
              const float* __restrict__ V, float* __restrict__ ctx)
{
    extern __shared__ uint32_t smu[];
    const uint32_t smem_u32 = (uint32_t)__cvta_generic_to_shared(smu);

    const int tid  = threadIdx.x;
    const int lane = tid & 31;
    const int w    = tid >> 5;
    const int g    = lane >> 2;
    const int t4   = lane & 3;

    const int b  = blockIdx.z;
    const int h  = blockIdx.y;
    const int q0 = blockIdx.x * 128;
    const size_t head_off = (size_t)(b * HH + h) * SS * DK;

    auto issueKV = [&](int t, int stg) {
        const float* Kt = K + head_off + ((size_t)t << 12);
        const float* Vt = V + head_off + ((size_t)t << 12);
        const int base = stg * ATT_STAGE;
#pragma unroll
        for (int i = 0; i < 8; i++) {
            int c = tid + (i << 7);
            int kv = c >> 4, d4 = (c & 15) << 2;
            cp_async16(smem_u32 + (base + kv*KS_S + d4)*4, Kt + (kv << 6) + d4);
            cp_async16(smem_u32 + (base + 64*KS_S + kv*VS_S + d4)*4, Vt + (kv << 6) + d4);
        }
        CP_COMMIT();
    };

    issueKV(0, 0);

    // ---- Q fragments for 32 rows (2 mi blocks), raw bits, fold 1/8
    uint32_t qa[2][8][4];
    {
        const float* Qb = Q + head_off + (size_t)(q0 + w*32) * DK;
#pragma unroll
        for (int mi = 0; mi < 2; mi++) {
#pragma unroll
            for (int ks = 0; ks < 8; ks++) {
                const float* Qm = Qb + (size_t)(mi*16) * DK;
                qa[mi][ks][0] = __float_as_uint(Qm[(size_t)g       * DK + ks*8 + t4    ] * 0.125f);
                qa[mi][ks][1] = __float_as_uint(Qm[(size_t)(g + 8) * DK + ks*8 + t4    ] * 0.125f);
                qa[mi][ks][2] = __float_as_uint(Qm[(size_t)g       * DK + ks*8 + t4 + 4] * 0.125f);
                qa[mi][ks][3] = __float_as_uint(Qm[(size_t)(g + 8) * DK + ks*8 + t4 + 4] * 0.125f);
            }
        }
    }

    float o[2][8][4];
#pragma unroll
    for (int mi = 0; mi < 2; mi++)
#pragma unroll
        for (int ni = 0; ni < 8; ni++)
#pragma unroll
            for (int r = 0; r < 4; r++) o[mi][ni][r] = 0.f;
    float mr[2][2], lr[2][2];
#pragma unroll
    for (int mi = 0; mi < 2; mi++) {
        mr[mi][0] = -CUDART_INF_F; mr[mi][1] = -CUDART_INF_F;
        lr[mi][0] = 0.f; lr[mi][1] = 0.f;
    }

    const int s0l = (lane & ~3) | (t4 >> 1);
    const int s1l = s0l + 2;

    for (int t = 0; t < SS / 64; ++t) {
        asm volatile("cp.async.wait_group 0;");
        __syncthreads();
        if (t + 1 < SS / 64) issueKV(t + 1, (t + 1) & 1);

        const uint32_t* Kst = smu + (t & 1) * ATT_STAGE;
        const uint32_t* Vst = Kst + 64*KS_S;

        // ---- S = Q @ K^T  (two mi blocks share each K fragment)
        float s[2][8][4];
#pragma unroll
        for (int mi = 0; mi < 2; mi++)
#pragma unroll
            for (int ni = 0; ni < 8; ni++)
#pragma unroll
                for (int r = 0; r < 4; r++) s[mi][ni][r] = 0.f;
#pragma unroll
        for (int ks = 0; ks < 8; ks++) {
#pragma unroll
            for (int ni = 0; ni < 8; ni++) {
                const uint32_t* kp = Kst + (ni*8 + g)*KS_S + ks*8 + t4;
                const uint32_t b0 = kp[0], b1 = kp[4];
                mma_tf32(s[0][ni][0], s[0][ni][1], s[0][ni][2], s[0][ni][3],
                         qa[0][ks][0], qa[0][ks][1], qa[0][ks][2], qa[0][ks][3], b0, b1);
                mma_tf32(s[1][ni][0], s[1][ni][1], s[1][ni][2], s[1][ni][3],
                         qa[1][ks][0], qa[1][ks][1], qa[1][ks][2], qa[1][ks][3], b0, b1);
            }
        }

        // ---- online softmax per mi block (rows g, g+8; quad reduction)
#pragma unroll
        for (int mi = 0; mi < 2; mi++) {
            float mx0 = -CUDART_INF_F, mx1 = -CUDART_INF_F;
#pragma unroll
            for (int ni = 0; ni < 8; ni++) {
                mx0 = fmaxf(mx0, fmaxf(s[mi][ni][0], s[mi][ni][1]));
                mx1 = fmaxf(mx1, fmaxf(s[mi][ni][2], s[mi][ni][3]));
            }
            mx0 = fmaxf(mx0, __shfl_xor_sync(0xffffffffu, mx0, 1));
            mx0 = fmaxf(mx0, __shfl_xor_sync(0xffffffffu, mx0, 2));
            mx1 = fmaxf(mx1, __shfl_xor_sync(0xffffffffu, mx1, 1));
            mx1 = fmaxf(mx1, __shfl_xor_sync(0xffffffffu, mx1, 2));

            float mn0 = fmaxf(mr[mi][0], mx0), mn1 = fmaxf(mr[mi][1], mx1);
            float alpha0 = __expf(mr[mi][0] - mn0), alpha1 = __expf(mr[mi][1] - mn1);
            mr[mi][0] = mn0; mr[mi][1] = mn1;

            float ps0 = 0.f, ps1 = 0.f;
#pragma unroll
            for (int ni = 0; ni < 8; ni++) {
                s[mi][ni][0] = __expf(s[mi][ni][0] - mn0);
                s[mi][ni][1] = __expf(s[mi][ni][1] - mn0);
                s[mi][ni][2] = __expf(s[mi][ni][2] - mn1);
                s[mi][ni][3] = __expf(s[mi][ni][3] - mn1);
                ps0 += s[mi][ni][0] + s[mi][ni][1];
                ps1 += s[mi][ni][2] + s[mi][ni][3];
            }
            ps0 += __shfl_xor_sync(0xffffffffu, ps0, 1);
            ps0 += __shfl_xor_sync(0xffffffffu, ps0, 2);
            ps1 += __shfl_xor_sync(0xffffffffu, ps1, 1);
            ps1 += __shfl_xor_sync(0xffffffffu, ps1, 2);
            lr[mi][0] = lr[mi][0] * alpha0 + ps0;
            lr[mi][1] = lr[mi][1] * alpha1 + ps1;
#pragma unroll
            for (int ni = 0; ni < 8; ni++) {
                o[mi][ni][0] *= alpha0; o[mi][ni][1] *= alpha0;
                o[mi][ni][2] *= alpha1; o[mi][ni][3] *= alpha1;
            }
        }

        // ---- O += P @ V ; C-frag -> A-frag via shfl; V frags shared by 2 mi
#pragma unroll
        for (int ks = 0; ks < 8; ks++) {
            uint32_t pa[2][4];
#pragma unroll
            for (int mi = 0; mi < 2; mi++) {
                float v00 = __shfl_sync(0xffffffffu, s[mi][ks][0], s0l);
                float v01 = __shfl_sync(0xffffffffu, s[mi][ks][1], s0l);
                float a0f = (t4 & 1) ? v01 : v00;
                float v10 = __shfl_sync(0xffffffffu, s[mi][ks][0], s1l);
                float v11 = __shfl_sync(0xffffffffu, s[mi][ks][1], s1l);
                float a2f = (t4 & 1) ? v11 : v10;
                float w00 = __shfl_sync(0xffffffffu, s[mi][ks][2], s0l);
                float w01 = __shfl_sync(0xffffffffu, s[mi][ks][3], s0l);
                float a1f = (t4 & 1) ? w01 : w00;
                float w10 = __shfl_sync(0xffffffffu, s[mi][ks][2], s1l);
                float w11 = __shfl_sync(0xffffffffu, s[mi][ks][3], s1l);
                float a3f = (t4 & 1) ? w11 : w10;
                pa[mi][0] = __float_as_uint(f2tf_f(a0f));
                pa[mi][1] = __float_as_uint(f2tf_f(a1f));
                pa[mi][2] = __float_as_uint(f2tf_f(a2f));
                pa[mi][3] = __float_as_uint(f2tf_f(a3f));
            }
#pragma unroll
            for (int ni = 0; ni < 8; ni++) {
                const uint32_t* vp = Vst + (ks*8 + t4)*VS_S + ni*8 + g;
                const uint32_t b0 = vp[0], b1 = vp[4*VS_S];
                mma_tf32(o[0][ni][0], o[0][ni][1], o[0][ni][2], o[0][ni][3],
                         pa[0][0], pa[0][1], pa[0][2], pa[0][3], b0, b1);
                mma_tf32(o[1][ni][0], o[1][ni][1], o[1][ni][2], o[1][ni][3],
                         pa[1][0], pa[1][1], pa[1][2], pa[1][3], b0, b1);
            }
        }
    }

    // ---- epilogue: ctx = O / l, rounded to tf32 for the Wo GEMM
#pragma unroll
    for (int mi = 0; mi < 2; mi++) {
        float inv0 = 1.f / lr[mi][0], inv1 = 1.f / lr[mi][1];
        const int q_r0 = q0 + w*32 + mi*16 + g;
#pragma unroll
        for (int ni = 0; ni < 8; ni++) {
            const int d = h*64 + ni*8 + 2*t4;
            float2 o0 = {f2tf_f(o[mi][ni][0] * inv0), f2tf_f(o[mi][ni][1] * inv0)};
            float2 o1 = {f2tf_f(o[mi][ni][2] * inv1), f2tf_f(o[mi][ni][3] * inv1)};
            *(float2*)&ctx[(size_t)(b * SS + q_r0    ) * DD + d] = o0;
            *(float2*)&ctx[(size_t)(b * SS + q_r0 + 8) * DD + d] = o1;
        }
    }
}

// ---------------------------------------------------------------------------
extern "C" void kernel_launch(void* const* d_in, const int* in_sizes, int n_in,
                              void* d_out, int out_size)
{
    const float* x  = (const float*)d_in[0];
    const float* Wq = (const float*)d_in[1];
    const float* bq = (const float*)d_in[2];
    const float* Wk = (const float*)d_in[3];
    const float* bk = (const float*)d_in[4];
    const float* Wv = (const float*)d_in[5];
    const float* bv = (const float*)d_in[6];
    const float* Wo = (const float*)d_in[7];
    const float* bo = (const float*)d_in[8];
    float* out = (float*)d_out;

    float *xT, *Wt, *Qb, *Kb, *Vb, *Cb;
    cudaGetSymbolAddress((void**)&xT, g_xT);
    cudaGetSymbolAddress((void**)&Wt, g_Wt);
    cudaGetSymbolAddress((void**)&Qb, g_Q);
    cudaGetSymbolAddress((void**)&Kb, g_K);
    cudaGetSymbolAddress((void**)&Vb, g_V);
    cudaGetSymbolAddress((void**)&Cb, g_ctx);
    float* Wt0 = Wt;
    float* Wt1 = Wt + (size_t)DD*DD;
    float* Wt2 = Wt + 2*(size_t)DD*DD;
    float* Wt3 = Wt + 3*(size_t)DD*DD;

    // Pre-round inputs to tf32
    const int xn4 = MM*DD/4, wn4 = DD*DD/4;
    tf32ify<<<(xn4+255)/256, 256>>>((const float4*)x,  (float4*)xT,  xn4);
    tf32ify<<<(wn4+255)/256, 256>>>((const float4*)Wq, (float4*)Wt0, wn4);
    tf32ify<<<(wn4+255)/256, 256>>>((const float4*)Wk, (float4*)Wt1, wn4);
    tf32ify<<<(wn4+255)/256, 256>>>((const float4*)Wv, (float4*)Wt2, wn4);
    tf32ify<<<(wn4+255)/256, 256>>>((const float4*)Wo, (float4*)Wt3, wn4);

    dim3 gemm_grid(DD / 128, MM / 128);   // (8, 64)

    cudaFuncSetAttribute((const void*)gemm_tc3<true>,
                         cudaFuncAttributeMaxDynamicSharedMemorySize, GEMM_SMEM);
    cudaFuncSetAttribute((const void*)gemm_tc3<false>,
                         cudaFuncAttributeMaxDynamicSharedMemorySize, GEMM_SMEM);
    cudaFuncSetAttribute((const void*)attn_tc4,
                         cudaFuncAttributeMaxDynamicSharedMemorySize, ATT_SMEM);

    gemm_tc3<true><<<gemm_grid, 256, GEMM_SMEM>>>(xT, Wt0, bq, Qb);
    gemm_tc3<true><<<gemm_grid, 256, GEMM_SMEM>>>(xT, Wt1, bk, Kb);
    gemm_tc3<true><<<gemm_grid, 256, GEMM_SMEM>>>(xT, Wt2, bv, Vb);

    attn_tc4<<<dim3(SS / 128, HH, BB), 128, ATT_SMEM>>>(Qb, Kb, Vb, Cb);

    gemm_tc3<false><<<gemm_grid, 256, GEMM_SMEM>>>(Cb, Wt3, bo, out);
}

// round 7
// speedup vs baseline: 22.9383x; 1.7634x over previous
#include <cuda_runtime.h>
#include <cuda_fp16.h>
#include <math_constants.h>
#include <cstdint>

// Problem constants
#define BB 4
#define SS 2048
#define DD 1024
#define HH 16
#define DK 64
#define MM (BB*SS)          // 8192 rows
#define KDIM 1024

// Scratch in device globals (no allocation allowed)
__device__ __half g_xh[MM*DD];           // f16 x (row-major)
__device__ __half g_Wh[4][DD*DD];        // f16 TRANSPOSED weights [n][k]
__device__ __half g_Qh[BB*HH*SS*DK];     // [b,h,s,d]
__device__ __half g_Kh[BB*HH*SS*DK];     // [b,h,s,d]
__device__ __half g_Vth[BB*HH*DK*SS];    // [b,h,d,s]  (transposed)
__device__ __half g_ctxh[BB*SS*DD];      // f16 ctx

__device__ __forceinline__ uint32_t packh2(float lo, float hi) {
    __half2 h = __float22half2_rn(make_float2(lo, hi));
    return *(uint32_t*)&h;
}

__device__ __forceinline__ void mma_f16(float& d0, float& d1, float& d2, float& d3,
                                        uint32_t a0, uint32_t a1, uint32_t a2, uint32_t a3,
                                        uint32_t b0, uint32_t b1) {
    asm volatile(
        "mma.sync.aligned.m16n8k16.row.col.f32.f16.f16.f32 "
        "{%0,%1,%2,%3}, {%4,%5,%6,%7}, {%8,%9}, {%0,%1,%2,%3};"
        : "+f"(d0), "+f"(d1), "+f"(d2), "+f"(d3)
        : "r"(a0), "r"(a1), "r"(a2), "r"(a3), "r"(b0), "r"(b1));
}

__device__ __forceinline__ void cp_async16(uint32_t dst, const void* src) {
    asm volatile("cp.async.cg.shared.global [%0], [%1], 16;" :: "r"(dst), "l"(src));
}
#define CP_COMMIT() asm volatile("cp.async.commit_group;")

// ---------------------------------------------------------------------------
// Prep: fp32 -> f16 copy (vectorized)
// ---------------------------------------------------------------------------
__global__ __launch_bounds__(256)
void h16ify(const float4* __restrict__ in, uint2* __restrict__ out, int n4)
{
    int i = blockIdx.x * 256 + threadIdx.x;
    if (i < n4) {
        float4 v = in[i];
        uint2 o;
        o.x = packh2(v.x, v.y);
        o.y = packh2(v.z, v.w);
        out[i] = o;
    }
}

// Prep: transpose + convert weights: in[K][N] fp32 -> out[N][K] f16
__global__ __launch_bounds__(256)
void wtrans_h(const float* __restrict__ in, __half* __restrict__ out)
{
    __shared__ float t[32][33];
    const int bx = blockIdx.x * 32, by = blockIdx.y * 32;
    const int tx = threadIdx.x & 31, ty = threadIdx.x >> 5;
#pragma unroll
    for (int i = 0; i < 4; i++) {
        int k = by + ty + i*8;
        t[ty + i*8][tx] = in[(size_t)k*DD + bx + tx];
    }
    __syncthreads();
#pragma unroll
    for (int i = 0; i < 4; i++) {
        int n = bx + ty + i*8;
        out[(size_t)n*DD + by + tx] = __float2half_rn(t[tx][ty + i*8]);
    }
}

// ---------------------------------------------------------------------------
// F16 tensor-core GEMM, cp.async 3-stage pipeline.
// C = A[M,1024](f16) @ W[1024,1024] + bias. 128x128x32 tiles, 8 warps
// (2m x 4n), warp tile 64x32, mma.m16n8k16. A and WT rows padded to
// 20 words (40 halves) -> conflict-free fragment LDS.
// MODE: 0 = fp32 out row-major; 1 = f16 split-heads [b,h,s,d];
//       2 = f16 split-heads transposed [b,h,d,s]
// ---------------------------------------------------------------------------
#define GSW 20                      // row stride in words
#define G_ROW_B (GSW*4)             // 80 bytes
#define G_AB (128*G_ROW_B)          // 10240 bytes per operand
#define G_STAGE_B (2*G_AB)          // 20480 bytes
#define GEMM_SMEM (3*G_STAGE_B)

template<int MODE>
__global__ __launch_bounds__(256, 2)
void gemm_h(const __half* __restrict__ A, const __half* __restrict__ WT,
            const float* __restrict__ bias, void* __restrict__ Cout)
{
    extern __shared__ uint8_t smraw[];
    const uint32_t smem_b = (uint32_t)__cvta_generic_to_shared(smraw);
    const uint32_t* smu = (const uint32_t*)smraw;

    const int tid  = threadIdx.x;
    const int lane = tid & 31;
    const int warp = tid >> 5;
    const int g    = lane >> 2;
    const int t4   = lane & 3;
    const int wm   = warp >> 2;   // 0..1
    const int wn   = warp & 3;    // 0..3

    const int m0 = blockIdx.y * 128;
    const int n0 = blockIdx.x * 128;
    const int nk = KDIM / 32;     // 32

    auto issue = [&](int kb, int stg) {
        const uint32_t base = smem_b + stg * G_STAGE_B;
#pragma unroll
        for (int i = 0; i < 2; i++) {
            int c = tid + i*256;              // 0..511
            int row = c >> 2, c4 = c & 3;
            cp_async16(base + row*G_ROW_B + c4*16,
                       A + (size_t)(m0 + row)*KDIM + kb*32 + c4*8);
        }
#pragma unroll
        for (int i = 0; i < 2; i++) {
            int c = tid + i*256;
            int row = c >> 2, c4 = c & 3;
            cp_async16(base + G_AB + row*G_ROW_B + c4*16,
                       WT + (size_t)(n0 + row)*KDIM + kb*32 + c4*8);
        }
        CP_COMMIT();
    };

    issue(0, 0);
    issue(1, 1);

    float acc[4][4][4];
#pragma unroll
    for (int mi = 0; mi < 4; mi++)
#pragma unroll
        for (int ni = 0; ni < 4; ni++)
#pragma unroll
            for (int r = 0; r < 4; r++) acc[mi][ni][r] = 0.f;

    for (int kb = 0; kb < nk; ++kb) {
        if (kb + 2 < nk) asm volatile("cp.async.wait_group 1;");
        else             asm volatile("cp.async.wait_group 0;");
        __syncthreads();
        if (kb + 2 < nk) issue(kb + 2, (kb + 2) % 3);

        const uint32_t* As = smu + (kb % 3) * (G_STAGE_B/4);
        const uint32_t* Bs = As + G_AB/4;

#pragma unroll
        for (int ks = 0; ks < 2; ++ks) {
            uint32_t au[4][4], bu[4][2];
#pragma unroll
            for (int mi = 0; mi < 4; mi++) {
                const uint32_t* ap = As + (wm*64 + mi*16 + g)*GSW + ks*8 + t4;
                au[mi][0] = ap[0];
                au[mi][1] = ap[8*GSW];
                au[mi][2] = ap[4];
                au[mi][3] = ap[8*GSW + 4];
            }
#pragma unroll
            for (int ni = 0; ni < 4; ni++) {
                const uint32_t* bp = Bs + (wn*32 + ni*8 + g)*GSW + ks*8 + t4;
                bu[ni][0] = bp[0];
                bu[ni][1] = bp[4];
            }
#pragma unroll
            for (int mi = 0; mi < 4; mi++)
#pragma unroll
                for (int ni = 0; ni < 4; ni++)
                    mma_f16(acc[mi][ni][0], acc[mi][ni][1], acc[mi][ni][2], acc[mi][ni][3],
                            au[mi][0], au[mi][1], au[mi][2], au[mi][3],
                            bu[ni][0], bu[ni][1]);
        }
    }

    // Epilogue. C-frag: c0,c1 = row g, cols 2t4,2t4+1 ; c2,c3 = row g+8.
#pragma unroll
    for (int mi = 0; mi < 4; mi++) {
#pragma unroll
        for (int ni = 0; ni < 4; ni++) {
            const int n = n0 + wn*32 + ni*8 + 2*t4;
            float2 bia = *(const float2*)&bias[n];
            const int mg = m0 + wm*64 + mi*16 + g;
            float v00 = acc[mi][ni][0] + bia.x, v01 = acc[mi][ni][1] + bia.y;
            float v10 = acc[mi][ni][2] + bia.x, v11 = acc[mi][ni][3] + bia.y;
            if (MODE == 0) {
                float* C = (float*)Cout;
                *(float2*)&C[(size_t)mg * DD + n]      = make_float2(v00, v01);
                *(float2*)&C[(size_t)(mg+8) * DD + n]  = make_float2(v10, v11);
            } else if (MODE == 1) {
                __half* C = (__half*)Cout;
                int h = n >> 6, d = n & 63;
                int b0 = mg >> 11, s0 = mg & (SS-1);
                *(uint32_t*)&C[(((size_t)(b0*HH + h)*SS + s0) << 6) + d] = packh2(v00, v01);
                int b1 = (mg+8) >> 11, s1 = (mg+8) & (SS-1);
                *(uint32_t*)&C[(((size_t)(b1*HH + h)*SS + s1) << 6) + d] = packh2(v10, v11);
            } else {
                __half* C = (__half*)Cout;
                int h = n >> 6, d = n & 63;
                int b0 = mg >> 11, s0 = mg & (SS-1);
                int b1 = (mg+8) >> 11, s1 = (mg+8) & (SS-1);
                size_t base0 = ((size_t)(b0*HH + h)*DK + d) * SS;
                size_t base1 = ((size_t)(b1*HH + h)*DK + d) * SS;
                C[base0 + s0]      = __float2half_rn(v00);
                C[base0 + SS + s0] = __float2half_rn(v01);   // d+1 row
                C[base1 + s1]      = __float2half_rn(v10);
                C[base1 + SS + s1] = __float2half_rn(v11);
            }
        }
    }
}

// ---------------------------------------------------------------------------
// F16 tensor-core flash attention, mi=2 (32 q-rows/warp, 128/CTA).
// K smem [kv][d] f16 stride 72 halves; Vt smem [d][kv] f16 stride 72.
// m16n8k16: P C-frag -> A-frag is a pure register pack (no shfl).
// cp.async double-buffered KV, one barrier per tile.
// ---------------------------------------------------------------------------
#define AKV_ROW_B 144                   // 72 halves * 2
#define AKV_TILE_B (64*AKV_ROW_B)       // 9216
#define ATT_STAGE_B (2*AKV_TILE_B)      // 18432
#define ATT_SMEM (2*ATT_STAGE_B)

__global__ __launch_bounds__(128, 2)
void attn_h(const __half* __restrict__ Q, const __half* __restrict__ K,
            const __half* __restrict__ Vt, __half* __restrict__ ctx)
{
    extern __shared__ uint32_t smu[];
    const uint32_t smem_b = (uint32_t)__cvta_generic_to_shared(smu);

    const int tid  = threadIdx.x;
    const int lane = tid & 31;
    const int w    = tid >> 5;
    const int g    = lane >> 2;
    const int t4   = lane & 3;

    const int b  = blockIdx.z;
    const int h  = blockIdx.y;
    const int q0 = blockIdx.x * 128;
    const size_t head_off  = (size_t)(b * HH + h) * SS * DK;   // for Q,K [s][d]
    const size_t head_offT = (size_t)(b * HH + h) * DK * SS;   // for Vt [d][s]

    auto issueKV = [&](int t, int stg) {
        const __half* Kt = K + head_off + ((size_t)t << 12);   // t*64*64
        const uint32_t base = smem_b + stg * ATT_STAGE_B;
#pragma unroll
        for (int i = 0; i < 4; i++) {
            int c = tid + (i << 7);            // 0..511
            int row = c >> 3, c8 = c & 7;
            cp_async16(base + row*AKV_ROW_B + c8*16, Kt + (row << 6) + c8*8);
        }
        const __half* Vp = Vt + head_offT + (t << 6);          // col offset t*64
        const uint32_t vbase = base + AKV_TILE_B;
#pragma unroll
        for (int i = 0; i < 4; i++) {
            int c = tid + (i << 7);
            int row = c >> 3, c8 = c & 7;      // row = d, c8 = kv chunk
            cp_async16(vbase + row*AKV_ROW_B + c8*16, Vp + (size_t)row * SS + c8*8);
        }
        CP_COMMIT();
    };

    issueKV(0, 0);

    // ---- Q fragments (persistent), f16 pairs, fold 1/8 (exact)
    const __half2 qs = __float2half2_rn(0.125f);
    uint32_t qa[2][4][4];
    {
        const __half* Qb = Q + head_off + (size_t)(q0 + w*32) * DK;
#pragma unroll
        for (int mi = 0; mi < 2; mi++) {
            const __half* Qm = Qb + (size_t)(mi*16) * DK;
#pragma unroll
            for (int ks = 0; ks < 4; ks++) {
                __half2 p0 = __hmul2(*(const __half2*)&Qm[(size_t)g     *DK + ks*16 + 2*t4    ], qs);
                __half2 p1 = __hmul2(*(const __half2*)&Qm[(size_t)(g+8) *DK + ks*16 + 2*t4    ], qs);
                __half2 p2 = __hmul2(*(const __half2*)&Qm[(size_t)g     *DK + ks*16 + 2*t4 + 8], qs);
                __half2 p3 = __hmul2(*(const __half2*)&Qm[(size_t)(g+8) *DK + ks*16 + 2*t4 + 8], qs);
                qa[mi][ks][0] = *(uint32_t*)&p0;
                qa[mi][ks][1] = *(uint32_t*)&p1;
                qa[mi][ks][2] = *(uint32_t*)&p2;
                qa[mi][ks][3] = *(uint32_t*)&p3;
            }
        }
    }

    float o[2][8][4];
#pragma unroll
    for (int mi = 0; mi < 2; mi++)
#pragma unroll
        for (int ni = 0; ni < 8; ni++)
#pragma unroll
            for (int r = 0; r < 4; r++) o[mi][ni][r] = 0.f;
    float mr[2][2], lr[2][2];
#pragma unroll
    for (int mi = 0; mi < 2; mi++) {
        mr[mi][0] = -CUDART_INF_F; mr[mi][1] = -CUDART_INF_F;
        lr[mi][0] = 0.f; lr[mi][1] = 0.f;
    }

    for (int t = 0; t < SS / 64; ++t) {
        asm volatile("cp.async.wait_group 0;");
        __syncthreads();
        if (t + 1 < SS / 64) issueKV(t + 1, (t + 1) & 1);

        const uint32_t* Kst = smu + (t & 1) * (ATT_STAGE_B/4);
        const uint32_t* Vst = Kst + AKV_TILE_B/4;

        // ---- S = Q @ K^T  (K-frag shared by both mi blocks)
        float s[2][8][4];
#pragma unroll
        for (int mi = 0; mi < 2; mi++)
#pragma unroll
            for (int ni = 0; ni < 8; ni++)
#pragma unroll
                for (int r = 0; r < 4; r++) s[mi][ni][r] = 0.f;
#pragma unroll
        for (int ks = 0; ks < 4; ks++) {
#pragma unroll
            for (int ni = 0; ni < 8; ni++) {
                const uint32_t* kp = Kst + (ni*8 + g)*36 + ks*8 + t4;
                const uint32_t b0 = kp[0], b1 = kp[4];
                mma_f16(s[0][ni][0], s[0][ni][1], s[0][ni][2], s[0][ni][3],
                        qa[0][ks][0], qa[0][ks][1], qa[0][ks][2], qa[0][ks][3], b0, b1);
                mma_f16(s[1][ni][0], s[1][ni][1], s[1][ni][2], s[1][ni][3],
                        qa[1][ks][0], qa[1][ks][1], qa[1][ks][2], qa[1][ks][3], b0, b1);
            }
        }

        // ---- online softmax per mi block (rows g, g+8; quad reduction)
#pragma unroll
        for (int mi = 0; mi < 2; mi++) {
            float mx0 = -CUDART_INF_F, mx1 = -CUDART_INF_F;
#pragma unroll
            for (int ni = 0; ni < 8; ni++) {
                mx0 = fmaxf(mx0, fmaxf(s[mi][ni][0], s[mi][ni][1]));
                mx1 = fmaxf(mx1, fmaxf(s[mi][ni][2], s[mi][ni][3]));
            }
            mx0 = fmaxf(mx0, __shfl_xor_sync(0xffffffffu, mx0, 1));
            mx0 = fmaxf(mx0, __shfl_xor_sync(0xffffffffu, mx0, 2));
            mx1 = fmaxf(mx1, __shfl_xor_sync(0xffffffffu, mx1, 1));
            mx1 = fmaxf(mx1, __shfl_xor_sync(0xffffffffu, mx1, 2));

            float mn0 = fmaxf(mr[mi][0], mx0), mn1 = fmaxf(mr[mi][1], mx1);
            float alpha0 = __expf(mr[mi][0] - mn0), alpha1 = __expf(mr[mi][1] - mn1);
            mr[mi][0] = mn0; mr[mi][1] = mn1;

            float ps0 = 0.f, ps1 = 0.f;
#pragma unroll
            for (int ni = 0; ni < 8; ni++) {
                s[mi][ni][0] = __expf(s[mi][ni][0] - mn0);
                s[mi][ni][1] = __expf(s[mi][ni][1] - mn0);
                s[mi][ni][2] = __expf(s[mi][ni][2] - mn1);
                s[mi][ni][3] = __expf(s[mi][ni][3] - mn1);
                ps0 += s[mi][ni][0] + s[mi][ni][1];
                ps1 += s[mi][ni][2] + s[mi][ni][3];
            }
            ps0 += __shfl_xor_sync(0xffffffffu, ps0, 1);
            ps0 += __shfl_xor_sync(0xffffffffu, ps0, 2);
            ps1 += __shfl_xor_sync(0xffffffffu, ps1, 1);
            ps1 += __shfl_xor_sync(0xffffffffu, ps1, 2);
            lr[mi][0] = lr[mi][0] * alpha0 + ps0;
            lr[mi][1] = lr[mi][1] * alpha1 + ps1;
#pragma unroll
            for (int ni = 0; ni < 8; ni++) {
                o[mi][ni][0] *= alpha0; o[mi][ni][1] *= alpha0;
                o[mi][ni][2] *= alpha1; o[mi][ni][3] *= alpha1;
            }
        }

        // ---- O += P @ V ; C-frag -> A-frag = direct register pack
#pragma unroll
        for (int ks = 0; ks < 4; ks++) {
            uint32_t pa[2][4];
#pragma unroll
            for (int mi = 0; mi < 2; mi++) {
                pa[mi][0] = packh2(s[mi][2*ks  ][0], s[mi][2*ks  ][1]);
                pa[mi][1] = packh2(s[mi][2*ks  ][2], s[mi][2*ks  ][3]);
                pa[mi][2] = packh2(s[mi][2*ks+1][0], s[mi][2*ks+1][1]);
                pa[mi][3] = packh2(s[mi][2*ks+1][2], s[mi][2*ks+1][3]);
            }
#pragma unroll
            for (int ni = 0; ni < 8; ni++) {
                const uint32_t* vp = Vst + (ni*8 + g)*36 + ks*8 + t4;
                const uint32_t b0 = vp[0], b1 = vp[4];
                mma_f16(o[0][ni][0], o[0][ni][1], o[0][ni][2], o[0][ni][3],
                        pa[0][0], pa[0][1], pa[0][2], pa[0][3], b0, b1);
                mma_f16(o[1][ni][0], o[1][ni][1], o[1][ni][2], o[1][ni][3],
                        pa[1][0], pa[1][1], pa[1][2], pa[1][3], b0, b1);
            }
        }
    }

    // ---- epilogue: ctx(f16) = O / l
#pragma unroll
    for (int mi = 0; mi < 2; mi++) {
        float inv0 = 1.f / lr[mi][0], inv1 = 1.f / lr[mi][1];
        const int q_r0 = q0 + w*32 + mi*16 + g;
#pragma unroll
        for (int ni = 0; ni < 8; ni++) {
            const int d = h*64 + ni*8 + 2*t4;
            *(uint32_t*)&ctx[(size_t)(b * SS + q_r0    ) * DD + d] =
                packh2(o[mi][ni][0]*inv0, o[mi][ni][1]*inv0);
            *(uint32_t*)&ctx[(size_t)(b * SS + q_r0 + 8) * DD + d] =
                packh2(o[mi][ni][2]*inv1, o[mi][ni][3]*inv1);
        }
    }
}

// ---------------------------------------------------------------------------
extern "C" void kernel_launch(void* const* d_in, const int* in_sizes, int n_in,
                              void* d_out, int out_size)
{
    const float* x  = (const float*)d_in[0];
    const float* Wq = (const float*)d_in[1];
    const float* bq = (const float*)d_in[2];
    const float* Wk = (const float*)d_in[3];
    const float* bk = (const float*)d_in[4];
    const float* Wv = (const float*)d_in[5];
    const float* bv = (const float*)d_in[6];
    const float* Wo = (const float*)d_in[7];
    const float* bo = (const float*)d_in[8];
    float* out = (float*)d_out;

    __half *xh, *Wh, *Qh, *Kh, *Vth, *ctxh;
    cudaGetSymbolAddress((void**)&xh,   g_xh);
    cudaGetSymbolAddress((void**)&Wh,   g_Wh);
    cudaGetSymbolAddress((void**)&Qh,   g_Qh);
    cudaGetSymbolAddress((void**)&Kh,   g_Kh);
    cudaGetSymbolAddress((void**)&Vth,  g_Vth);
    cudaGetSymbolAddress((void**)&ctxh, g_ctxh);
    __half* Wh0 = Wh;
    __half* Wh1 = Wh + (size_t)DD*DD;
    __half* Wh2 = Wh + 2*(size_t)DD*DD;
    __half* Wh3 = Wh + 3*(size_t)DD*DD;

    // Prep: x -> f16; W -> transposed f16
    const int xn4 = MM*DD/4;
    h16ify<<<(xn4+255)/256, 256>>>((const float4*)x, (uint2*)xh, xn4);
    dim3 tgrid(DD/32, DD/32);
    wtrans_h<<<tgrid, 256>>>(Wq, Wh0);
    wtrans_h<<<tgrid, 256>>>(Wk, Wh1);
    wtrans_h<<<tgrid, 256>>>(Wv, Wh2);
    wtrans_h<<<tgrid, 256>>>(Wo, Wh3);

    dim3 gemm_grid(DD / 128, MM / 128);   // (8, 64)

    cudaFuncSetAttribute((const void*)gemm_h<0>,
                         cudaFuncAttributeMaxDynamicSharedMemorySize, GEMM_SMEM);
    cudaFuncSetAttribute((const void*)gemm_h<1>,
                         cudaFuncAttributeMaxDynamicSharedMemorySize, GEMM_SMEM);
    cudaFuncSetAttribute((const void*)gemm_h<2>,
                         cudaFuncAttributeMaxDynamicSharedMemorySize, GEMM_SMEM);
    cudaFuncSetAttribute((const void*)attn_h,
                         cudaFuncAttributeMaxDynamicSharedMemorySize, ATT_SMEM);

    gemm_h<1><<<gemm_grid, 256, GEMM_SMEM>>>(xh, Wh0, bq, Qh);
    gemm_h<1><<<gemm_grid, 256, GEMM_SMEM>>>(xh, Wh1, bk, Kh);
    gemm_h<2><<<gemm_grid, 256, GEMM_SMEM>>>(xh, Wh2, bv, Vth);

    attn_h<<<dim3(SS / 128, HH, BB), 128, ATT_SMEM>>>(Qh, Kh, Vth, ctxh);

    gemm_h<0><<<gemm_grid, 256, GEMM_SMEM>>>(ctxh, Wh3, bo, out);
}

// round 8
// speedup vs baseline: 24.3998x; 1.0637x over previous
#include <cuda_runtime.h>
#include <cuda_fp16.h>
#include <math_constants.h>
#include <cstdint>

// Problem constants
#define BB 4
#define SS 2048
#define DD 1024
#define HH 16
#define DK 64
#define MM (BB*SS)          // 8192 rows
#define KDIM 1024

// Scratch in device globals (no allocation allowed)
__device__ __half g_xh[MM*DD];           // f16 x (row-major)
__device__ __half g_Wh[4][DD*DD];        // f16 TRANSPOSED weights [n][k]
__device__ __half g_Qh[BB*HH*SS*DK];     // [b,h,s,d]
__device__ __half g_Kh[BB*HH*SS*DK];     // [b,h,s,d]
__device__ __half g_Vth[BB*HH*DK*SS];    // [b,h,d,s]  (transposed)
__device__ __half g_ctxh[BB*SS*DD];      // f16 ctx

#define ONES_H2 0x3C003C00u
#define LOG2E 1.4426950408889634f

__device__ __forceinline__ uint32_t packh2(float lo, float hi) {
    __half2 h = __float22half2_rn(make_float2(lo, hi));
    return *(uint32_t*)&h;
}
__device__ __forceinline__ uint32_t ex2h2(uint32_t a) {
    uint32_t d;
    asm("ex2.approx.f16x2 %0, %1;" : "=r"(d) : "r"(a));
    return d;
}
__device__ __forceinline__ uint32_t hsub2u(uint32_t a, uint32_t b) {
    __half2 r = __hsub2(*(__half2*)&a, *(__half2*)&b);
    return *(uint32_t*)&r;
}

__device__ __forceinline__ void mma_f16(float& d0, float& d1, float& d2, float& d3,
                                        uint32_t a0, uint32_t a1, uint32_t a2, uint32_t a3,
                                        uint32_t b0, uint32_t b1) {
    asm volatile(
        "mma.sync.aligned.m16n8k16.row.col.f32.f16.f16.f32 "
        "{%0,%1,%2,%3}, {%4,%5,%6,%7}, {%8,%9}, {%0,%1,%2,%3};"
        : "+f"(d0), "+f"(d1), "+f"(d2), "+f"(d3)
        : "r"(a0), "r"(a1), "r"(a2), "r"(a3), "r"(b0), "r"(b1));
}

__device__ __forceinline__ void cp_async16(uint32_t dst, const void* src) {
    asm volatile("cp.async.cg.shared.global [%0], [%1], 16;" :: "r"(dst), "l"(src));
}
#define CP_COMMIT() asm volatile("cp.async.commit_group;")

// ---------------------------------------------------------------------------
// Prep: fp32 -> f16 copy (vectorized)
// ---------------------------------------------------------------------------
__global__ __launch_bounds__(256)
void h16ify(const float4* __restrict__ in, uint2* __restrict__ out, int n4)
{
    int i = blockIdx.x * 256 + threadIdx.x;
    if (i < n4) {
        float4 v = in[i];
        uint2 o;
        o.x = packh2(v.x, v.y);
        o.y = packh2(v.z, v.w);
        out[i] = o;
    }
}

// Prep: transpose + convert 4 weights in one launch (z selects weight)
__global__ __launch_bounds__(256)
void wtrans_h4(const float* __restrict__ W0, const float* __restrict__ W1,
               const float* __restrict__ W2, const float* __restrict__ W3,
               __half* __restrict__ outbase)
{
    __shared__ float t[32][33];
    const float* in = (blockIdx.z == 0) ? W0 : (blockIdx.z == 1) ? W1
                    : (blockIdx.z == 2) ? W2 : W3;
    __half* out = outbase + (size_t)blockIdx.z * DD * DD;
    const int bx = blockIdx.x * 32, by = blockIdx.y * 32;
    const int tx = threadIdx.x & 31, ty = threadIdx.x >> 5;
#pragma unroll
    for (int i = 0; i < 4; i++) {
        int k = by + ty + i*8;
        t[ty + i*8][tx] = in[(size_t)k*DD + bx + tx];
    }
    __syncthreads();
#pragma unroll
    for (int i = 0; i < 4; i++) {
        int n = bx + ty + i*8;
        out[(size_t)n*DD + by + tx] = __float2half_rn(t[tx][ty + i*8]);
    }
}

// ---------------------------------------------------------------------------
// F16 tensor-core GEMM, cp.async 3-stage pipeline. (unchanged from R7)
// MODE: 0 = fp32 out row-major; 1 = f16 split-heads [b,h,s,d];
//       2 = f16 split-heads transposed [b,h,d,s]
// ---------------------------------------------------------------------------
#define GSW 20                      // row stride in words
#define G_ROW_B (GSW*4)             // 80 bytes
#define G_AB (128*G_ROW_B)          // 10240 bytes per operand
#define G_STAGE_B (2*G_AB)          // 20480 bytes
#define GEMM_SMEM (3*G_STAGE_B)

template<int MODE>
__global__ __launch_bounds__(256, 2)
void gemm_h(const __half* __restrict__ A, const __half* __restrict__ WT,
            const float* __restrict__ bias, void* __restrict__ Cout)
{
    extern __shared__ uint8_t smraw[];
    const uint32_t smem_b = (uint32_t)__cvta_generic_to_shared(smraw);
    const uint32_t* smu = (const uint32_t*)smraw;

    const int tid  = threadIdx.x;
    const int lane = tid & 31;
    const int warp = tid >> 5;
    const int g    = lane >> 2;
    const int t4   = lane & 3;
    const int wm   = warp >> 2;   // 0..1
    const int wn   = warp & 3;    // 0..3

    const int m0 = blockIdx.y * 128;
    const int n0 = blockIdx.x * 128;
    const int nk = KDIM / 32;     // 32

    auto issue = [&](int kb, int stg) {
        const uint32_t base = smem_b + stg * G_STAGE_B;
#pragma unroll
        for (int i = 0; i < 2; i++) {
            int c = tid + i*256;              // 0..511
            int row = c >> 2, c4 = c & 3;
            cp_async16(base + row*G_ROW_B + c4*16,
                       A + (size_t)(m0 + row)*KDIM + kb*32 + c4*8);
        }
#pragma unroll
        for (int i = 0; i < 2; i++) {
            int c = tid + i*256;
            int row = c >> 2, c4 = c & 3;
            cp_async16(base + G_AB + row*G_ROW_B + c4*16,
                       WT + (size_t)(n0 + row)*KDIM + kb*32 + c4*8);
        }
        CP_COMMIT();
    };

    issue(0, 0);
    issue(1, 1);

    float acc[4][4][4];
#pragma unroll
    for (int mi = 0; mi < 4; mi++)
#pragma unroll
        for (int ni = 0; ni < 4; ni++)
#pragma unroll
            for (int r = 0; r < 4; r++) acc[mi][ni][r] = 0.f;

    for (int kb = 0; kb < nk; ++kb) {
        if (kb + 2 < nk) asm volatile("cp.async.wait_group 1;");
        else             asm volatile("cp.async.wait_group 0;");
        __syncthreads();
        if (kb + 2 < nk) issue(kb + 2, (kb + 2) % 3);

        const uint32_t* As = smu + (kb % 3) * (G_STAGE_B/4);
        const uint32_t* Bs = As + G_AB/4;

#pragma unroll
        for (int ks = 0; ks < 2; ++ks) {
            uint32_t au[4][4], bu[4][2];
#pragma unroll
            for (int mi = 0; mi < 4; mi++) {
                const uint32_t* ap = As + (wm*64 + mi*16 + g)*GSW + ks*8 + t4;
                au[mi][0] = ap[0];
                au[mi][1] = ap[8*GSW];
                au[mi][2] = ap[4];
                au[mi][3] = ap[8*GSW + 4];
            }
#pragma unroll
            for (int ni = 0; ni < 4; ni++) {
                const uint32_t* bp = Bs + (wn*32 + ni*8 + g)*GSW + ks*8 + t4;
                bu[ni][0] = bp[0];
                bu[ni][1] = bp[4];
            }
#pragma unroll
            for (int mi = 0; mi < 4; mi++)
#pragma unroll
                for (int ni = 0; ni < 4; ni++)
                    mma_f16(acc[mi][ni][0], acc[mi][ni][1], acc[mi][ni][2], acc[mi][ni][3],
                            au[mi][0], au[mi][1], au[mi][2], au[mi][3],
                            bu[ni][0], bu[ni][1]);
        }
    }

    // Epilogue. C-frag: c0,c1 = row g, cols 2t4,2t4+1 ; c2,c3 = row g+8.
#pragma unroll
    for (int mi = 0; mi < 4; mi++) {
#pragma unroll
        for (int ni = 0; ni < 4; ni++) {
            const int n = n0 + wn*32 + ni*8 + 2*t4;
            float2 bia = *(const float2*)&bias[n];
            const int mg = m0 + wm*64 + mi*16 + g;
            float v00 = acc[mi][ni][0] + bia.x, v01 = acc[mi][ni][1] + bia.y;
            float v10 = acc[mi][ni][2] + bia.x, v11 = acc[mi][ni][3] + bia.y;
            if (MODE == 0) {
                float* C = (float*)Cout;
                *(float2*)&C[(size_t)mg * DD + n]      = make_float2(v00, v01);
                *(float2*)&C[(size_t)(mg+8) * DD + n]  = make_float2(v10, v11);
            } else if (MODE == 1) {
                __half* C = (__half*)Cout;
                int h = n >> 6, d = n & 63;
                int b0 = mg >> 11, s0 = mg & (SS-1);
                *(uint32_t*)&C[(((size_t)(b0*HH + h)*SS + s0) << 6) + d] = packh2(v00, v01);
                int b1 = (mg+8) >> 11, s1 = (mg+8) & (SS-1);
                *(uint32_t*)&C[(((size_t)(b1*HH + h)*SS + s1) << 6) + d] = packh2(v10, v11);
            } else {
                __half* C = (__half*)Cout;
                int h = n >> 6, d = n & 63;
                int b0 = mg >> 11, s0 = mg & (SS-1);
                int b1 = (mg+8) >> 11, s1 = (mg+8) & (SS-1);
                size_t base0 = ((size_t)(b0*HH + h)*DK + d) * SS;
                size_t base1 = ((size_t)(b1*HH + h)*DK + d) * SS;
                C[base0 + s0]      = __float2half_rn(v00);
                C[base0 + SS + s0] = __float2half_rn(v01);   // d+1 row
                C[base1 + s1]      = __float2half_rn(v10);
                C[base1 + SS + s1] = __float2half_rn(v11);
            }
        }
    }
}

// ---------------------------------------------------------------------------
// F16 flash attention, mi=2 (32 q-rows/warp, 128/CTA).
// Softmax vectorized: scores in log2 domain (log2e folded into Q scale),
// p = ex2.approx.f16x2(pack(s)-m) producing PV A-frags directly.
// Row-sum l via ones-B MMA (fp32 tensor-core accumulation, no shfl reduce).
// ---------------------------------------------------------------------------
#define AKV_ROW_B 144                   // 72 halves * 2
#define AKV_TILE_B (64*AKV_ROW_B)       // 9216
#define ATT_STAGE_B (2*AKV_TILE_B)      // 18432
#define ATT_SMEM (2*ATT_STAGE_B)

__global__ __launch_bounds__(128, 2)
void attn_h2(const __half* __restrict__ Q, const __half* __restrict__ K,
             const __half* __restrict__ Vt, __half* __restrict__ ctx)
{
    extern __shared__ uint32_t smu[];
    const uint32_t smem_b = (uint32_t)__cvta_generic_to_shared(smu);

    const int tid  = threadIdx.x;
    const int lane = tid & 31;
    const int w    = tid >> 5;
    const int g    = lane >> 2;
    const int t4   = lane & 3;

    const int b  = blockIdx.z;
    const int h  = blockIdx.y;
    const int q0 = blockIdx.x * 128;
    const size_t head_off  = (size_t)(b * HH + h) * SS * DK;   // Q,K [s][d]
    const size_t head_offT = (size_t)(b * HH + h) * DK * SS;   // Vt [d][s]

    auto issueKV = [&](int t, int stg) {
        const __half* Kt = K + head_off + ((size_t)t << 12);   // t*64*64
        const uint32_t base = smem_b + stg * ATT_STAGE_B;
#pragma unroll
        for (int i = 0; i < 4; i++) {
            int c = tid + (i << 7);            // 0..511
            int row = c >> 3, c8 = c & 7;
            cp_async16(base + row*AKV_ROW_B + c8*16, Kt + (row << 6) + c8*8);
        }
        const __half* Vp = Vt + head_offT + (t << 6);          // col offset t*64
        const uint32_t vbase = base + AKV_TILE_B;
#pragma unroll
        for (int i = 0; i < 4; i++) {
            int c = tid + (i << 7);
            int row = c >> 3, c8 = c & 7;      // row = d, c8 = kv chunk
            cp_async16(vbase + row*AKV_ROW_B + c8*16, Vp + (size_t)row * SS + c8*8);
        }
        CP_COMMIT();
    };

    issueKV(0, 0);

    // ---- Q fragments (persistent), scale = (1/8)*log2e folded in
    const __half2 qs = __float2half2_rn(0.125f * LOG2E);
    uint32_t qa[2][4][4];
    {
        const __half* Qb = Q + head_off + (size_t)(q0 + w*32) * DK;
#pragma unroll
        for (int mi = 0; mi < 2; mi++) {
            const __half* Qm = Qb + (size_t)(mi*16) * DK;
#pragma unroll
            for (int ks = 0; ks < 4; ks++) {
                __half2 p0 = __hmul2(*(const __half2*)&Qm[(size_t)g     *DK + ks*16 + 2*t4    ], qs);
                __half2 p1 = __hmul2(*(const __half2*)&Qm[(size_t)(g+8) *DK + ks*16 + 2*t4    ], qs);
                __half2 p2 = __hmul2(*(const __half2*)&Qm[(size_t)g     *DK + ks*16 + 2*t4 + 8], qs);
                __half2 p3 = __hmul2(*(const __half2*)&Qm[(size_t)(g+8) *DK + ks*16 + 2*t4 + 8], qs);
                qa[mi][ks][0] = *(uint32_t*)&p0;
                qa[mi][ks][1] = *(uint32_t*)&p1;
                qa[mi][ks][2] = *(uint32_t*)&p2;
                qa[mi][ks][3] = *(uint32_t*)&p3;
            }
        }
    }

    float o[2][8][4];
#pragma unroll
    for (int mi = 0; mi < 2; mi++)
#pragma unroll
        for (int ni = 0; ni < 8; ni++)
#pragma unroll
            for (int r = 0; r < 4; r++) o[mi][ni][r] = 0.f;
    float mr[2][2], lr[2][2];
#pragma unroll
    for (int mi = 0; mi < 2; mi++) {
        mr[mi][0] = -CUDART_INF_F; mr[mi][1] = -CUDART_INF_F;
        lr[mi][0] = 0.f; lr[mi][1] = 0.f;
    }

    for (int t = 0; t < SS / 64; ++t) {
        asm volatile("cp.async.wait_group 0;");
        __syncthreads();
        if (t + 1 < SS / 64) issueKV(t + 1, (t + 1) & 1);

        const uint32_t* Kst = smu + (t & 1) * (ATT_STAGE_B/4);
        const uint32_t* Vst = Kst + AKV_TILE_B/4;

        // ---- S = Q @ K^T  (log2 domain; K-frag shared by both mi blocks)
        float s[2][8][4];
#pragma unroll
        for (int mi = 0; mi < 2; mi++)
#pragma unroll
            for (int ni = 0; ni < 8; ni++)
#pragma unroll
                for (int r = 0; r < 4; r++) s[mi][ni][r] = 0.f;
#pragma unroll
        for (int ks = 0; ks < 4; ks++) {
#pragma unroll
            for (int ni = 0; ni < 8; ni++) {
                const uint32_t* kp = Kst + (ni*8 + g)*36 + ks*8 + t4;
                const uint32_t b0 = kp[0], b1 = kp[4];
                mma_f16(s[0][ni][0], s[0][ni][1], s[0][ni][2], s[0][ni][3],
                        qa[0][ks][0], qa[0][ks][1], qa[0][ks][2], qa[0][ks][3], b0, b1);
                mma_f16(s[1][ni][0], s[1][ni][1], s[1][ni][2], s[1][ni][3],
                        qa[1][ks][0], qa[1][ks][1], qa[1][ks][2], qa[1][ks][3], b0, b1);
            }
        }

        // ---- softmax (log2 domain) -> e[][ni][2] = PV A-frag half2 pairs
        uint32_t e[2][8][2];
        float alpha[2][2];
#pragma unroll
        for (int mi = 0; mi < 2; mi++) {
            float mx0 = -CUDART_INF_F, mx1 = -CUDART_INF_F;
#pragma unroll
            for (int ni = 0; ni < 8; ni++) {
                mx0 = fmaxf(mx0, fmaxf(s[mi][ni][0], s[mi][ni][1]));
                mx1 = fmaxf(mx1, fmaxf(s[mi][ni][2], s[mi][ni][3]));
            }
            mx0 = fmaxf(mx0, __shfl_xor_sync(0xffffffffu, mx0, 1));
            mx0 = fmaxf(mx0, __shfl_xor_sync(0xffffffffu, mx0, 2));
            mx1 = fmaxf(mx1, __shfl_xor_sync(0xffffffffu, mx1, 1));
            mx1 = fmaxf(mx1, __shfl_xor_sync(0xffffffffu, mx1, 2));

            float mn0 = fmaxf(mr[mi][0], mx0), mn1 = fmaxf(mr[mi][1], mx1);
            alpha[mi][0] = exp2f(mr[mi][0] - mn0);
            alpha[mi][1] = exp2f(mr[mi][1] - mn1);
            mr[mi][0] = mn0; mr[mi][1] = mn1;

            uint32_t m2a, m2b;
            { __half2 ha = __float2half2_rn(mn0); m2a = *(uint32_t*)&ha;
              __half2 hb = __float2half2_rn(mn1); m2b = *(uint32_t*)&hb; }
#pragma unroll
            for (int ni = 0; ni < 8; ni++) {
                e[mi][ni][0] = ex2h2(hsub2u(packh2(s[mi][ni][0], s[mi][ni][1]), m2a));
                e[mi][ni][1] = ex2h2(hsub2u(packh2(s[mi][ni][2], s[mi][ni][3]), m2b));
            }
            // rescale O
#pragma unroll
            for (int ni = 0; ni < 8; ni++) {
                o[mi][ni][0] *= alpha[mi][0]; o[mi][ni][1] *= alpha[mi][0];
                o[mi][ni][2] *= alpha[mi][1]; o[mi][ni][3] *= alpha[mi][1];
            }
        }

        // ---- O += P @ V ; lsum via ones-B MMA (fp32 accum)
        float la[2][4] = {{0.f,0.f,0.f,0.f},{0.f,0.f,0.f,0.f}};
#pragma unroll
        for (int ks = 0; ks < 4; ks++) {
            const uint32_t pa00 = e[0][2*ks][0], pa01 = e[0][2*ks][1];
            const uint32_t pa02 = e[0][2*ks+1][0], pa03 = e[0][2*ks+1][1];
            const uint32_t pa10 = e[1][2*ks][0], pa11 = e[1][2*ks][1];
            const uint32_t pa12 = e[1][2*ks+1][0], pa13 = e[1][2*ks+1][1];
#pragma unroll
            for (int ni = 0; ni < 8; ni++) {
                const uint32_t* vp = Vst + (ni*8 + g)*36 + ks*8 + t4;
                const uint32_t b0 = vp[0], b1 = vp[4];
                mma_f16(o[0][ni][0], o[0][ni][1], o[0][ni][2], o[0][ni][3],
                        pa00, pa01, pa02, pa03, b0, b1);
                mma_f16(o[1][ni][0], o[1][ni][1], o[1][ni][2], o[1][ni][3],
                        pa10, pa11, pa12, pa13, b0, b1);
            }
            mma_f16(la[0][0], la[0][1], la[0][2], la[0][3],
                    pa00, pa01, pa02, pa03, ONES_H2, ONES_H2);
            mma_f16(la[1][0], la[1][1], la[1][2], la[1][3],
                    pa10, pa11, pa12, pa13, ONES_H2, ONES_H2);
        }
#pragma unroll
        for (int mi = 0; mi < 2; mi++) {
            lr[mi][0] = lr[mi][0] * alpha[mi][0] + la[mi][0];
            lr[mi][1] = lr[mi][1] * alpha[mi][1] + la[mi][2];
        }
    }

    // ---- epilogue: ctx(f16) = O / l
#pragma unroll
    for (int mi = 0; mi < 2; mi++) {
        float inv0 = 1.f / lr[mi][0], inv1 = 1.f / lr[mi][1];
        const int q_r0 = q0 + w*32 + mi*16 + g;
#pragma unroll
        for (int ni = 0; ni < 8; ni++) {
            const int d = h*64 + ni*8 + 2*t4;
            *(uint32_t*)&ctx[(size_t)(b * SS + q_r0    ) * DD + d] =
                packh2(o[mi][ni][0]*inv0, o[mi][ni][1]*inv0);
            *(uint32_t*)&ctx[(size_t)(b * SS + q_r0 + 8) * DD + d] =
                packh2(o[mi][ni][2]*inv1, o[mi][ni][3]*inv1);
        }
    }
}

// ---------------------------------------------------------------------------
extern "C" void kernel_launch(void* const* d_in, const int* in_sizes, int n_in,
                              void* d_out, int out_size)
{
    const float* x  = (const float*)d_in[0];
    const float* Wq = (const float*)d_in[1];
    const float* bq = (const float*)d_in[2];
    const float* Wk = (const float*)d_in[3];
    const float* bk = (const float*)d_in[4];
    const float* Wv = (const float*)d_in[5];
    const float* bv = (const float*)d_in[6];
    const float* Wo = (const float*)d_in[7];
    const float* bo = (const float*)d_in[8];
    float* out = (float*)d_out;

    __half *xh, *Wh, *Qh, *Kh, *Vth, *ctxh;
    cudaGetSymbolAddress((void**)&xh,   g_xh);
    cudaGetSymbolAddress((void**)&Wh,   g_Wh);
    cudaGetSymbolAddress((void**)&Qh,   g_Qh);
    cudaGetSymbolAddress((void**)&Kh,   g_Kh);
    cudaGetSymbolAddress((void**)&Vth,  g_Vth);
    cudaGetSymbolAddress((void**)&ctxh, g_ctxh);
    __half* Wh0 = Wh;
    __half* Wh1 = Wh + (size_t)DD*DD;
    __half* Wh2 = Wh + 2*(size_t)DD*DD;
    __half* Wh3 = Wh + 3*(size_t)DD*DD;

    // Prep: x -> f16; all 4 W -> transposed f16 (one launch)
    const int xn4 = MM*DD/4;
    h16ify<<<(xn4+255)/256, 256>>>((const float4*)x, (uint2*)xh, xn4);
    wtrans_h4<<<dim3(DD/32, DD/32, 4), 256>>>(Wq, Wk, Wv, Wo, Wh);

    dim3 gemm_grid(DD / 128, MM / 128);   // (8, 64)

    cudaFuncSetAttribute((const void*)gemm_h<0>,
                         cudaFuncAttributeMaxDynamicSharedMemorySize, GEMM_SMEM);
    cudaFuncSetAttribute((const void*)gemm_h<1>,
                         cudaFuncAttributeMaxDynamicSharedMemorySize, GEMM_SMEM);
    cudaFuncSetAttribute((const void*)gemm_h<2>,
                         cudaFuncAttributeMaxDynamicSharedMemorySize, GEMM_SMEM);
    cudaFuncSetAttribute((const void*)attn_h2,
                         cudaFuncAttributeMaxDynamicSharedMemorySize, ATT_SMEM);

    gemm_h<1><<<gemm_grid, 256, GEMM_SMEM>>>(xh, Wh0, bq, Qh);
    gemm_h<1><<<gemm_grid, 256, GEMM_SMEM>>>(xh, Wh1, bk, Kh);
    gemm_h<2><<<gemm_grid, 256, GEMM_SMEM>>>(xh, Wh2, bv, Vth);

    attn_h2<<<dim3(SS / 128, HH, BB), 128, ATT_SMEM>>>(Qh, Kh, Vth, ctxh);

    gemm_h<0><<<gemm_grid, 256, GEMM_SMEM>>>(ctxh, Wh3, bo, out);
}